// round 1
// baseline (speedup 1.0000x reference)
#include <cuda_runtime.h>
#include <math.h>
#include <stdint.h>

#define B_ 2
#define L_ 1024
#define HID 2048
#define NH 32
#define HD 64
#define NKV 8
#define INTER 8192
#define DSSM 2048
#define MH 32
#define MP 64
#define MS 64
#define MK 4
#define CONV_DIM (DSSM + 2*MS)          // 2176
#define PROJ_DIM (2*DSSM + 2*MS + MH)   // 4256
#define QKV_DIM (NH*HD + 2*NKV*HD)      // 3072
#define MROWS (B_*L_)                   // 2048

#define ATTN_IN 1.2f
#define ATTN_OUT 0.8f
#define KEY_MULT 0.7f
#define SSM_IN 1.1f
#define SSM_OUT 0.9f
#define GATE_MULT 0.9f
#define DOWN_MULT 0.8f
#define EPS_ 1e-5f

// ---------------- scratch (device globals; no allocation allowed) ----------------
__device__ float g_hs  [MROWS*HID];
__device__ float g_qkv [MROWS*QKV_DIM];
__device__ float g_ctx [MROWS*HID];
__device__ float g_proj[MROWS*PROJ_DIM];
__device__ float g_conv[MROWS*CONV_DIM];
__device__ float g_y   [MROWS*DSSM];
__device__ float g_gt  [MROWS*DSSM];
__device__ float g_as  [MROWS*HID];
__device__ float g_h   [MROWS*HID];
__device__ float g_hn  [MROWS*HID];
__device__ float g_gu  [(size_t)MROWS*2*INTER];
__device__ float g_act [(size_t)MROWS*INTER];

// ---------------- helpers ----------------
__device__ __forceinline__ float blockReduceSum256(float v) {
    __shared__ float sh[8];
    int lane = threadIdx.x & 31, w = threadIdx.x >> 5;
    #pragma unroll
    for (int o = 16; o; o >>= 1) v += __shfl_xor_sync(0xffffffffu, v, o);
    if (lane == 0) sh[w] = v;
    __syncthreads();
    v = (threadIdx.x < 8) ? sh[threadIdx.x] : 0.f;
    if (w == 0) {
        #pragma unroll
        for (int o = 4; o; o >>= 1) v += __shfl_xor_sync(0xffu, v, o);
    }
    return v;   // valid on thread 0
}

__device__ __forceinline__ float siluf(float x) { return x / (1.f + __expf(-x)); }

// ---------------- generic SGEMM:  C = alpha * A(MxK) @ B(NxK)^T + beta * Cin ----------------
#define GBM 128
#define GBN 128
#define GBK 8
__global__ __launch_bounds__(256) void sgemm_nt(
    int Mi, int Ni, int Ki, float alpha,
    const float* __restrict__ A, const float* __restrict__ Bw,
    float beta, const float* __restrict__ Cin, float* __restrict__ C)
{
    __shared__ float As[GBK][GBM];
    __shared__ float Bs[GBK][GBN];
    const int bm = blockIdx.y * GBM, bn = blockIdx.x * GBN;
    const int tid = threadIdx.x;
    const int lr = tid >> 1, lk = (tid & 1) * 4;
    const int ty = tid >> 4, tx = tid & 15;

    float acc[8][8];
    #pragma unroll
    for (int i = 0; i < 8; ++i)
        #pragma unroll
        for (int j = 0; j < 8; ++j) acc[i][j] = 0.f;

    const bool aValid = (bm + lr) < Mi;
    const bool bValid = (bn + lr) < Ni;
    const float* Aptr = A  + (size_t)(bm + lr) * Ki + lk;
    const float* Bptr = Bw + (size_t)(bn + lr) * Ki + lk;

    float4 av = aValid ? *(const float4*)Aptr : make_float4(0,0,0,0);
    float4 bv = bValid ? *(const float4*)Bptr : make_float4(0,0,0,0);

    for (int k0 = 0; k0 < Ki; k0 += GBK) {
        As[lk+0][lr] = av.x; As[lk+1][lr] = av.y; As[lk+2][lr] = av.z; As[lk+3][lr] = av.w;
        Bs[lk+0][lr] = bv.x; Bs[lk+1][lr] = bv.y; Bs[lk+2][lr] = bv.z; Bs[lk+3][lr] = bv.w;
        __syncthreads();

        Aptr += GBK; Bptr += GBK;
        float4 an = make_float4(0,0,0,0), bn4 = make_float4(0,0,0,0);
        if (k0 + GBK < Ki) {
            if (aValid) an  = *(const float4*)Aptr;
            if (bValid) bn4 = *(const float4*)Bptr;
        }

        #pragma unroll
        for (int kk = 0; kk < GBK; ++kk) {
            float af[8], bf[8];
            #pragma unroll
            for (int i = 0; i < 8; ++i) af[i] = As[kk][ty*8+i];
            #pragma unroll
            for (int j = 0; j < 8; ++j) bf[j] = Bs[kk][tx*8+j];
            #pragma unroll
            for (int i = 0; i < 8; ++i)
                #pragma unroll
                for (int j = 0; j < 8; ++j) acc[i][j] = fmaf(af[i], bf[j], acc[i][j]);
        }
        __syncthreads();
        av = an; bv = bn4;
    }

    #pragma unroll
    for (int i = 0; i < 8; ++i) {
        int row = bm + ty*8 + i;
        if (row >= Mi) continue;
        #pragma unroll
        for (int j = 0; j < 8; ++j) {
            int col = bn + tx*8 + j;
            if (col >= Ni) continue;
            size_t off = (size_t)row * Ni + col;
            float v = alpha * acc[i][j];
            if (beta != 0.f) v += beta * Cin[off];
            C[off] = v;
        }
    }
}

// ---------------- RMS norm: out = rms(x)*w ----------------
__global__ __launch_bounds__(256) void rms_kernel(
    const float* __restrict__ x, const float* __restrict__ w, float* __restrict__ out)
{
    int m = blockIdx.x;
    const float* xr = x + (size_t)m * HID;
    float v[8]; float ss = 0.f;
    #pragma unroll
    for (int k = 0; k < 8; ++k) { v[k] = xr[threadIdx.x + k*256]; ss += v[k]*v[k]; }
    ss = blockReduceSum256(ss);
    __shared__ float s_inv;
    if (threadIdx.x == 0) s_inv = rsqrtf(ss * (1.f/HID) + EPS_);
    __syncthreads();
    float inv = s_inv;
    float* o = out + (size_t)m * HID;
    #pragma unroll
    for (int k = 0; k < 8; ++k) { int c = threadIdx.x + k*256; o[c] = v[k]*inv*w[c]; }
}

// ---------------- RoPE in place on qkv (q heads + k heads, k scaled by KEY_MULT) -----
__global__ void rope_kernel(float* __restrict__ qkv, const int* __restrict__ positions) {
    int idx = blockIdx.x*256 + threadIdx.x;
    const int total = MROWS*(NH+NKV)*32;
    if (idx >= total) return;
    int i = idx & 31; int rest = idx >> 5;
    int head = rest % (NH+NKV); int ml = rest / (NH+NKV);
    int l = ml % L_;
    int col; float mult;
    if (head < NH) { col = head*HD; mult = 1.f; }
    else           { col = NH*HD + (head-NH)*HD; mult = KEY_MULT; }
    float* p = qkv + (size_t)ml*QKV_DIM + col;
    float inv = powf(1e11f, -(float)i/32.0f);
    float ang = (float)positions[l] * inv;
    float c = cosf(ang), s = sinf(ang);
    float x1 = p[i]*mult, x2 = p[i+32]*mult;
    p[i]    = x1*c - x2*s;
    p[i+32] = x2*c + x1*s;
}

// ---------------- Flash attention (causal, GQA 32q/8kv, HD=64) ----------------
__global__ __launch_bounds__(256) void attn_kernel(
    const float* __restrict__ qkv, float* __restrict__ ctx)
{
    __shared__ float Qt[64][64];  // [d][m]
    __shared__ float KP[64][64];  // K as [d][n], then reused as P [n][m]
    __shared__ float Vs[64][64];  // [n][d]
    const int tid = threadIdx.x;
    const int ty = tid >> 4, tx = tid & 15;
    const int qb = blockIdx.x, h = blockIdx.y, b = blockIdx.z;
    const int g = h >> 2;
    const int qcol = h*HD;
    const int kcol = NH*HD + g*HD;
    const int vcol = NH*HD + NKV*HD + g*HD;

    for (int i = tid; i < 64*16; i += 256) {
        int r = i >> 4, d4 = (i & 15) << 2;
        float4 v = *(const float4*)(qkv + (size_t)(b*L_ + qb*64 + r)*QKV_DIM + qcol + d4);
        Qt[d4+0][r]=v.x; Qt[d4+1][r]=v.y; Qt[d4+2][r]=v.z; Qt[d4+3][r]=v.w;
    }

    float acc[4][4]; float m_i[4], l_i[4];
    #pragma unroll
    for (int i = 0; i < 4; ++i) {
        m_i[i] = -1e30f; l_i[i] = 0.f;
        #pragma unroll
        for (int j = 0; j < 4; ++j) acc[i][j] = 0.f;
    }

    for (int j = 0; j <= qb; ++j) {
        __syncthreads();
        for (int i = tid; i < 64*16; i += 256) {
            int r = i >> 4, d4 = (i & 15) << 2;
            const float* rowp = qkv + (size_t)(b*L_ + j*64 + r)*QKV_DIM;
            float4 kv = *(const float4*)(rowp + kcol + d4);
            KP[d4+0][r]=kv.x; KP[d4+1][r]=kv.y; KP[d4+2][r]=kv.z; KP[d4+3][r]=kv.w;
            *(float4*)(&Vs[r][d4]) = *(const float4*)(rowp + vcol + d4);
        }
        __syncthreads();

        float s[4][4];
        #pragma unroll
        for (int i = 0; i < 4; ++i)
            #pragma unroll
            for (int jj = 0; jj < 4; ++jj) s[i][jj] = 0.f;
        #pragma unroll 8
        for (int kk = 0; kk < 64; ++kk) {
            float a[4], bb[4];
            #pragma unroll
            for (int i = 0; i < 4; ++i)  a[i]  = Qt[kk][ty*4+i];
            #pragma unroll
            for (int jj = 0; jj < 4; ++jj) bb[jj] = KP[kk][tx*4+jj];
            #pragma unroll
            for (int i = 0; i < 4; ++i)
                #pragma unroll
                for (int jj = 0; jj < 4; ++jj) s[i][jj] = fmaf(a[i], bb[jj], s[i][jj]);
        }
        const bool diag = (j == qb);
        #pragma unroll
        for (int i = 0; i < 4; ++i)
            #pragma unroll
            for (int jj = 0; jj < 4; ++jj) {
                bool masked = diag && ((tx*4+jj) > (ty*4+i));
                s[i][jj] = masked ? -1e30f : s[i][jj]*0.125f;
            }

        float p[4][4];
        #pragma unroll
        for (int i = 0; i < 4; ++i) {
            float rm = fmaxf(fmaxf(s[i][0], s[i][1]), fmaxf(s[i][2], s[i][3]));
            #pragma unroll
            for (int o = 8; o; o >>= 1) rm = fmaxf(rm, __shfl_xor_sync(0xffffffffu, rm, o));
            float mnew = fmaxf(m_i[i], rm);
            float rs = 0.f;
            #pragma unroll
            for (int jj = 0; jj < 4; ++jj) { p[i][jj] = __expf(s[i][jj] - mnew); rs += p[i][jj]; }
            #pragma unroll
            for (int o = 8; o; o >>= 1) rs += __shfl_xor_sync(0xffffffffu, rs, o);
            float corr = __expf(m_i[i] - mnew);
            l_i[i] = l_i[i]*corr + rs;
            m_i[i] = mnew;
            #pragma unroll
            for (int jj = 0; jj < 4; ++jj) acc[i][jj] *= corr;
        }

        __syncthreads();
        #pragma unroll
        for (int i = 0; i < 4; ++i)
            #pragma unroll
            for (int jj = 0; jj < 4; ++jj) KP[tx*4+jj][ty*4+i] = p[i][jj];
        __syncthreads();

        #pragma unroll 8
        for (int kk = 0; kk < 64; ++kk) {
            float a[4], bb[4];
            #pragma unroll
            for (int i = 0; i < 4; ++i)  a[i]  = KP[kk][ty*4+i];
            #pragma unroll
            for (int jj = 0; jj < 4; ++jj) bb[jj] = Vs[kk][tx*4+jj];
            #pragma unroll
            for (int i = 0; i < 4; ++i)
                #pragma unroll
                for (int jj = 0; jj < 4; ++jj) acc[i][jj] = fmaf(a[i], bb[jj], acc[i][jj]);
        }
    }

    #pragma unroll
    for (int i = 0; i < 4; ++i) {
        float invl = 1.f / l_i[i];
        #pragma unroll
        for (int jj = 0; jj < 4; ++jj)
            ctx[(size_t)(b*L_ + qb*64 + ty*4+i)*HID + h*HD + tx*4 + jj] = acc[i][jj]*invl;
    }
}

// ---------------- depthwise causal conv (MK=4) + mup + bias + SiLU ----------------
__global__ void conv_kernel(const float* __restrict__ proj, const float* __restrict__ cw,
                            const float* __restrict__ cb, float* __restrict__ out)
{
    int idx = blockIdx.x*256 + threadIdx.x;
    if (idx >= MROWS*CONV_DIM) return;
    int c = idx % CONV_DIM;
    int ml = idx / CONV_DIM;
    int l = ml % L_, b = ml / L_;
    float mupf = (c < DSSM) ? 0.9f : ((c < DSSM+MS) ? 0.8f : 1.1f);
    float s = 0.f;
    #pragma unroll
    for (int k = 0; k < MK; ++k) {
        int ls = l + k - (MK-1);
        if (ls >= 0) s += proj[(size_t)(b*L_+ls)*PROJ_DIM + DSSM + c] * cw[c*MK + k];
    }
    s = mupf*s + cb[c];
    out[idx] = siluf(s);
}

// ---------------- Mamba2 selective scan (per (b,h) block; state in registers) -----
#define SCT 32
__global__ __launch_bounds__(256) void scan_kernel(
    const float* __restrict__ conv, const float* __restrict__ proj,
    const float* __restrict__ A_log, const float* __restrict__ dt_bias,
    const float* __restrict__ Dp, float* __restrict__ y)
{
    const int b = blockIdx.x / MH, h = blockIdx.x % MH;
    const int tid = threadIdx.x;
    const int p = tid >> 2, sg = tid & 3, s0 = sg*16;
    const float Ah = -__expf(A_log[h]);
    const float Dh = Dp[h];
    const float dtb = dt_bias[h];
    float st[16];
    #pragma unroll
    for (int i = 0; i < 16; ++i) st[i] = 0.f;

    __shared__ float xs[SCT][64], Bsh[SCT][64], Csh[SCT][64], dts[SCT];

    for (int l0 = 0; l0 < L_; l0 += SCT) {
        __syncthreads();
        for (int i = tid; i < SCT*64; i += 256) {
            int t = i >> 6, c = i & 63;
            size_t base = (size_t)(b*L_ + l0 + t)*CONV_DIM;
            xs[t][c]  = conv[base + h*64 + c];
            Bsh[t][c] = conv[base + DSSM + c];
            Csh[t][c] = conv[base + DSSM + MS + c];
        }
        for (int i = tid; i < SCT; i += 256) {
            float r = proj[(size_t)(b*L_ + l0 + i)*PROJ_DIM + (PROJ_DIM-MH) + h] * 1.2f + dtb;
            dts[i] = (r > 20.f) ? r : log1pf(expf(r));   // softplus
        }
        __syncthreads();
        for (int t = 0; t < SCT; ++t) {
            float dt = dts[t];
            float dA = __expf(dt * Ah);
            float xv = xs[t][p];
            float coef = dt * xv;
            float acc = 0.f;
            #pragma unroll
            for (int ss = 0; ss < 16; ++ss) {
                st[ss] = st[ss]*dA + coef*Bsh[t][s0+ss];
                acc = fmaf(st[ss], Csh[t][s0+ss], acc);
            }
            acc += __shfl_xor_sync(0xffffffffu, acc, 1);
            acc += __shfl_xor_sync(0xffffffffu, acc, 2);
            if (sg == 0)
                y[(size_t)(b*L_ + l0 + t)*DSSM + h*64 + p] = acc + xv*Dh;
        }
    }
}

// ---------------- gating + RMS: gt = rms(y * silu(z)) * ssm_norm_w ----------------
__global__ __launch_bounds__(256) void gate_rms_kernel(
    const float* __restrict__ y, const float* __restrict__ proj,
    const float* __restrict__ w, float* __restrict__ out)
{
    int m = blockIdx.x;
    const float* yr = y + (size_t)m*DSSM;
    const float* zr = proj + (size_t)m*PROJ_DIM;   // z = first DSSM cols (mup = 1.0)
    float v[8]; float ss = 0.f;
    #pragma unroll
    for (int k = 0; k < 8; ++k) {
        int c = threadIdx.x + k*256;
        float z = zr[c];
        float gv = yr[c] * siluf(z);
        v[k] = gv; ss += gv*gv;
    }
    ss = blockReduceSum256(ss);
    __shared__ float s_inv;
    if (threadIdx.x == 0) s_inv = rsqrtf(ss * (1.f/DSSM) + EPS_);
    __syncthreads();
    float inv = s_inv;
    float* o = out + (size_t)m*DSSM;
    #pragma unroll
    for (int k = 0; k < 8; ++k) { int c = threadIdx.x + k*256; o[c] = v[k]*inv*w[c]; }
}

// ---------------- combine: h = as + residual ; hn = rms(h)*w ----------------
__global__ __launch_bounds__(256) void combine_kernel(
    const float* __restrict__ as_, const float* __restrict__ resid,
    const float* __restrict__ w, float* __restrict__ h, float* __restrict__ hn)
{
    int m = blockIdx.x;
    const float* ar = as_  + (size_t)m*HID;
    const float* rr = resid + (size_t)m*HID;
    float v[8]; float ss = 0.f;
    #pragma unroll
    for (int k = 0; k < 8; ++k) {
        int c = threadIdx.x + k*256;
        float hv = ar[c] + rr[c];
        v[k] = hv; ss += hv*hv;
    }
    ss = blockReduceSum256(ss);
    __shared__ float s_inv;
    if (threadIdx.x == 0) s_inv = rsqrtf(ss * (1.f/HID) + EPS_);
    __syncthreads();
    float inv = s_inv;
    float* ho = h + (size_t)m*HID;
    float* no = hn + (size_t)m*HID;
    #pragma unroll
    for (int k = 0; k < 8; ++k) {
        int c = threadIdx.x + k*256;
        ho[c] = v[k];
        no[c] = v[k]*inv*w[c];
    }
}

// ---------------- SwiGLU activation: act = silu(gate*0.9)*up ----------------
__global__ void act_kernel(const float* __restrict__ gu, float* __restrict__ act) {
    int idx = blockIdx.x*256 + threadIdx.x;
    if (idx >= MROWS*INTER) return;
    int m = idx / INTER, i = idx % INTER;
    const float* row = gu + (size_t)m*(2*INTER);
    float gate = row[i] * GATE_MULT;
    float up   = row[INTER + i];
    act[idx] = siluf(gate) * up;
}

// ---------------- host launcher ----------------
extern "C" void kernel_launch(void* const* d_in, const int* in_sizes, int n_in,
                              void* d_out, int out_size)
{
    const float* hidden      = (const float*)d_in[0];
    const int*   positions   = (const int*)  d_in[1];
    const float* w_in_ln     = (const float*)d_in[2];
    const float* qkv_w       = (const float*)d_in[3];
    const float* o_w         = (const float*)d_in[4];
    const float* in_proj_w   = (const float*)d_in[5];
    const float* conv_w      = (const float*)d_in[6];
    const float* conv_b      = (const float*)d_in[7];
    const float* A_log       = (const float*)d_in[8];
    const float* dt_bias     = (const float*)d_in[9];
    const float* Dp          = (const float*)d_in[10];
    const float* ssm_norm_w  = (const float*)d_in[11];
    const float* out_proj_w  = (const float*)d_in[12];
    const float* w_pre_ff_ln = (const float*)d_in[13];
    const float* gate_up_w   = (const float*)d_in[14];
    const float* down_w      = (const float*)d_in[15];
    float* out = (float*)d_out;

    float *hs, *qkv, *ctx, *proj, *conv, *y, *gt, *as_, *h, *hn, *gu, *act;
    cudaGetSymbolAddress((void**)&hs,  g_hs);
    cudaGetSymbolAddress((void**)&qkv, g_qkv);
    cudaGetSymbolAddress((void**)&ctx, g_ctx);
    cudaGetSymbolAddress((void**)&proj,g_proj);
    cudaGetSymbolAddress((void**)&conv,g_conv);
    cudaGetSymbolAddress((void**)&y,   g_y);
    cudaGetSymbolAddress((void**)&gt,  g_gt);
    cudaGetSymbolAddress((void**)&as_, g_as);
    cudaGetSymbolAddress((void**)&h,   g_h);
    cudaGetSymbolAddress((void**)&hn,  g_hn);
    cudaGetSymbolAddress((void**)&gu,  g_gu);
    cudaGetSymbolAddress((void**)&act, g_act);

    // 1. input RMS norm
    rms_kernel<<<MROWS, 256>>>(hidden, w_in_ln, hs);

    // 2. qkv = (hs*ATTN_IN) @ qkv_w^T   and   proj = (hs*SSM_IN) @ in_proj_w^T
    sgemm_nt<<<dim3(QKV_DIM/GBN, MROWS/GBM), 256>>>(MROWS, QKV_DIM, HID, ATTN_IN,
                                                    hs, qkv_w, 0.f, nullptr, qkv);
    sgemm_nt<<<dim3((PROJ_DIM+GBN-1)/GBN, MROWS/GBM), 256>>>(MROWS, PROJ_DIM, HID, SSM_IN,
                                                    hs, in_proj_w, 0.f, nullptr, proj);

    // 3. RoPE (q; k scaled by KEY_MULT)
    rope_kernel<<<(MROWS*(NH+NKV)*32 + 255)/256, 256>>>(qkv, positions);

    // 4. attention
    attn_kernel<<<dim3(L_/64, NH, B_), 256>>>(qkv, ctx);

    // 5. as = ATTN_OUT * ctx @ o_w^T
    sgemm_nt<<<dim3(HID/GBN, MROWS/GBM), 256>>>(MROWS, HID, HID, ATTN_OUT,
                                                ctx, o_w, 0.f, nullptr, as_);

    // 6. mamba: conv -> scan -> gate+rms -> out_proj (accumulated into as)
    conv_kernel<<<(MROWS*CONV_DIM + 255)/256, 256>>>(proj, conv_w, conv_b, conv);
    scan_kernel<<<B_*MH, 256>>>(conv, proj, A_log, dt_bias, Dp, y);
    gate_rms_kernel<<<MROWS, 256>>>(y, proj, ssm_norm_w, gt);
    sgemm_nt<<<dim3(HID/GBN, MROWS/GBM), 256>>>(MROWS, HID, DSSM, SSM_OUT,
                                                gt, out_proj_w, 1.f, as_, as_);

    // 7. combine + pre-FF RMS
    combine_kernel<<<MROWS, 256>>>(as_, hidden, w_pre_ff_ln, h, hn);

    // 8. MLP
    sgemm_nt<<<dim3(2*INTER/GBN, MROWS/GBM), 256>>>(MROWS, 2*INTER, HID, 1.f,
                                                    hn, gate_up_w, 0.f, nullptr, gu);
    act_kernel<<<(MROWS*INTER + 255)/256, 256>>>(gu, act);
    sgemm_nt<<<dim3(HID/GBN, MROWS/GBM), 256>>>(MROWS, HID, INTER, DOWN_MULT,
                                                act, down_w, 1.f, h, out);
    (void)in_sizes; (void)n_in; (void)out_size;
}

// round 2
// speedup vs baseline: 2.3232x; 2.3232x over previous
#include <cuda_runtime.h>
#include <math.h>
#include <stdint.h>

#define B_ 2
#define L_ 1024
#define HID 2048
#define NH 32
#define HD 64
#define NKV 8
#define INTER 8192
#define DSSM 2048
#define MH 32
#define MP 64
#define MS 64
#define MK 4
#define CONV_DIM (DSSM + 2*MS)          // 2176
#define PROJ_DIM (2*DSSM + 2*MS + MH)   // 4256
#define QKV_DIM (NH*HD + 2*NKV*HD)      // 3072
#define MROWS (B_*L_)                   // 2048

#define ATTN_IN 1.2f
#define ATTN_OUT 0.8f
#define KEY_MULT 0.7f
#define SSM_IN 1.1f
#define SSM_OUT 0.9f
#define GATE_MULT 0.9f
#define DOWN_MULT 0.8f
#define EPS_ 1e-5f

// ---------------- scratch (device globals; no allocation allowed) ----------------
__device__ float g_hs  [MROWS*HID];
__device__ float g_qkv [MROWS*QKV_DIM];
__device__ float g_ctx [MROWS*HID];
__device__ float g_proj[MROWS*PROJ_DIM];
__device__ float g_conv[MROWS*CONV_DIM];
__device__ float g_y   [MROWS*DSSM];
__device__ float g_gt  [MROWS*DSSM];
__device__ float g_as  [MROWS*HID];
__device__ float g_h   [MROWS*HID];
__device__ float g_hn  [MROWS*HID];
__device__ float g_gu  [(size_t)MROWS*2*INTER];
__device__ float g_act [(size_t)MROWS*INTER];

// ---------------- helpers ----------------
__device__ __forceinline__ float blockReduceSum256(float v) {
    __shared__ float sh[8];
    int lane = threadIdx.x & 31, w = threadIdx.x >> 5;
    #pragma unroll
    for (int o = 16; o; o >>= 1) v += __shfl_xor_sync(0xffffffffu, v, o);
    if (lane == 0) sh[w] = v;
    __syncthreads();
    v = (threadIdx.x < 8) ? sh[threadIdx.x] : 0.f;
    if (w == 0) {
        #pragma unroll
        for (int o = 4; o; o >>= 1) v += __shfl_xor_sync(0xffu, v, o);
    }
    return v;   // valid on thread 0
}

__device__ __forceinline__ float siluf(float x) { return x / (1.f + __expf(-x)); }

__device__ __forceinline__ uint32_t f2tf32(float f) {
    uint32_t u; asm("cvt.rna.tf32.f32 %0, %1;" : "=r"(u) : "f"(f)); return u;
}

__device__ __forceinline__ void mma_tf32(float* c, const uint32_t* a, const uint32_t* b) {
    asm volatile(
        "mma.sync.aligned.m16n8k8.row.col.f32.tf32.tf32.f32 "
        "{%0,%1,%2,%3}, {%4,%5,%6,%7}, {%8,%9}, {%0,%1,%2,%3};"
        : "+f"(c[0]), "+f"(c[1]), "+f"(c[2]), "+f"(c[3])
        : "r"(a[0]), "r"(a[1]), "r"(a[2]), "r"(a[3]), "r"(b[0]), "r"(b[1]));
}

// ---------------- TF32 tensor-core GEMM:  C = alpha * A(MxK) @ B(NxK)^T + beta * Cin
// block tile 128x128x32, 8 warps (2x4), warp tile 64x32 via m16n8k8.
// smem layout: row-major M(N) x K-tile with 36-float row stride -> fragment
// gathers map to banks as (4g + t) mod 32: conflict-free.
#define TBM 128
#define TBN 128
#define TBK 32
#define TST 36
__global__ __launch_bounds__(256) void gemm_tf32(
    int Mi, int Ni, int Ki, float alpha,
    const float* __restrict__ A, const float* __restrict__ Bw,
    float beta, const float* __restrict__ Cin, float* __restrict__ C)
{
    __shared__ uint32_t As[TBM*TST];
    __shared__ uint32_t Bs[TBN*TST];

    const int tid = threadIdx.x;
    const int bm = blockIdx.y * TBM, bn = blockIdx.x * TBN;
    const int lr = tid >> 1;            // 0..127 tile row
    const int lc = (tid & 1) * 16;      // 0 or 16 within k-tile
    const int warp = tid >> 5, lane = tid & 31;
    const int g = lane >> 2, t = lane & 3;
    const int wm = (warp >> 2) * 64;    // warp m offset (0 or 64)
    const int wn = (warp & 3) * 32;     // warp n offset (0,32,64,96)

    const float* Aptr = A  + (size_t)(bm + lr) * Ki + lc;   // M rows always valid
    const bool bValid = (bn + lr) < Ni;
    const float* Bptr = Bw + (size_t)(bn + lr) * Ki + lc;

    float4 av[4], bv[4];
    #pragma unroll
    for (int q = 0; q < 4; ++q) {
        av[q] = *(const float4*)(Aptr + q*4);
        bv[q] = bValid ? *(const float4*)(Bptr + q*4) : make_float4(0,0,0,0);
    }

    float acc[4][4][4];
    #pragma unroll
    for (int i = 0; i < 4; ++i)
        #pragma unroll
        for (int j = 0; j < 4; ++j)
            #pragma unroll
            for (int r = 0; r < 4; ++r) acc[i][j][r] = 0.f;

    for (int k0 = 0; k0 < Ki; k0 += TBK) {
        // commit prefetched regs -> smem (with tf32 rounding)
        uint32_t* ad = As + lr*TST + lc;
        uint32_t* bd = Bs + lr*TST + lc;
        #pragma unroll
        for (int q = 0; q < 4; ++q) {
            *(uint4*)(ad + q*4) = make_uint4(f2tf32(av[q].x), f2tf32(av[q].y),
                                             f2tf32(av[q].z), f2tf32(av[q].w));
            *(uint4*)(bd + q*4) = make_uint4(f2tf32(bv[q].x), f2tf32(bv[q].y),
                                             f2tf32(bv[q].z), f2tf32(bv[q].w));
        }
        __syncthreads();

        Aptr += TBK; Bptr += TBK;
        if (k0 + TBK < Ki) {
            #pragma unroll
            for (int q = 0; q < 4; ++q) {
                av[q] = *(const float4*)(Aptr + q*4);
                bv[q] = bValid ? *(const float4*)(Bptr + q*4) : make_float4(0,0,0,0);
            }
        }

        #pragma unroll
        for (int ks = 0; ks < TBK/8; ++ks) {
            uint32_t af[4][4];
            #pragma unroll
            for (int i = 0; i < 4; ++i) {
                const uint32_t* base = As + (wm + i*16 + g)*TST + ks*8 + t;
                af[i][0] = base[0];
                af[i][1] = base[8*TST];
                af[i][2] = base[4];
                af[i][3] = base[8*TST + 4];
            }
            uint32_t bf[4][2];
            #pragma unroll
            for (int j = 0; j < 4; ++j) {
                const uint32_t* base = Bs + (wn + j*8 + g)*TST + ks*8 + t;
                bf[j][0] = base[0];
                bf[j][1] = base[4];
            }
            #pragma unroll
            for (int i = 0; i < 4; ++i)
                #pragma unroll
                for (int j = 0; j < 4; ++j)
                    mma_tf32(acc[i][j], af[i], bf[j]);
        }
        __syncthreads();
    }

    // epilogue: c0 (g,2t) c1 (g,2t+1) c2 (g+8,2t) c3 (g+8,2t+1)
    #pragma unroll
    for (int i = 0; i < 4; ++i) {
        int row0 = bm + wm + i*16 + g;
        #pragma unroll
        for (int j = 0; j < 4; ++j) {
            int col = bn + wn + j*8 + 2*t;
            if (col >= Ni) continue;
            size_t o0 = (size_t)row0 * Ni + col;
            size_t o1 = (size_t)(row0 + 8) * Ni + col;
            float2 v0 = make_float2(alpha*acc[i][j][0], alpha*acc[i][j][1]);
            float2 v1 = make_float2(alpha*acc[i][j][2], alpha*acc[i][j][3]);
            if (beta != 0.f) {
                float2 e0 = *(const float2*)(Cin + o0);
                float2 e1 = *(const float2*)(Cin + o1);
                v0.x += beta*e0.x; v0.y += beta*e0.y;
                v1.x += beta*e1.x; v1.y += beta*e1.y;
            }
            *(float2*)(C + o0) = v0;
            *(float2*)(C + o1) = v1;
        }
    }
}

// ---------------- RMS norm: out = rms(x)*w ----------------
__global__ __launch_bounds__(256) void rms_kernel(
    const float* __restrict__ x, const float* __restrict__ w, float* __restrict__ out)
{
    int m = blockIdx.x;
    const float* xr = x + (size_t)m * HID;
    float v[8]; float ss = 0.f;
    #pragma unroll
    for (int k = 0; k < 8; ++k) { v[k] = xr[threadIdx.x + k*256]; ss += v[k]*v[k]; }
    ss = blockReduceSum256(ss);
    __shared__ float s_inv;
    if (threadIdx.x == 0) s_inv = rsqrtf(ss * (1.f/HID) + EPS_);
    __syncthreads();
    float inv = s_inv;
    float* o = out + (size_t)m * HID;
    #pragma unroll
    for (int k = 0; k < 8; ++k) { int c = threadIdx.x + k*256; o[c] = v[k]*inv*w[c]; }
}

// ---------------- RoPE in place on qkv ----------------
__global__ void rope_kernel(float* __restrict__ qkv, const int* __restrict__ positions) {
    int idx = blockIdx.x*256 + threadIdx.x;
    const int total = MROWS*(NH+NKV)*32;
    if (idx >= total) return;
    int i = idx & 31; int rest = idx >> 5;
    int head = rest % (NH+NKV); int ml = rest / (NH+NKV);
    int l = ml % L_;
    int col; float mult;
    if (head < NH) { col = head*HD; mult = 1.f; }
    else           { col = NH*HD + (head-NH)*HD; mult = KEY_MULT; }
    float* p = qkv + (size_t)ml*QKV_DIM + col;
    float inv = powf(1e11f, -(float)i/32.0f);
    float ang = (float)positions[l] * inv;
    float c = cosf(ang), s = sinf(ang);
    float x1 = p[i]*mult, x2 = p[i+32]*mult;
    p[i]    = x1*c - x2*s;
    p[i+32] = x2*c + x1*s;
}

// ---------------- Flash attention (causal, GQA 32q/8kv, HD=64) ----------------
__global__ __launch_bounds__(256) void attn_kernel(
    const float* __restrict__ qkv, float* __restrict__ ctx)
{
    __shared__ float Qt[64][64];
    __shared__ float KP[64][64];
    __shared__ float Vs[64][64];
    const int tid = threadIdx.x;
    const int ty = tid >> 4, tx = tid & 15;
    const int qb = blockIdx.x, h = blockIdx.y, b = blockIdx.z;
    const int g = h >> 2;
    const int qcol = h*HD;
    const int kcol = NH*HD + g*HD;
    const int vcol = NH*HD + NKV*HD + g*HD;

    for (int i = tid; i < 64*16; i += 256) {
        int r = i >> 4, d4 = (i & 15) << 2;
        float4 v = *(const float4*)(qkv + (size_t)(b*L_ + qb*64 + r)*QKV_DIM + qcol + d4);
        Qt[d4+0][r]=v.x; Qt[d4+1][r]=v.y; Qt[d4+2][r]=v.z; Qt[d4+3][r]=v.w;
    }

    float acc[4][4]; float m_i[4], l_i[4];
    #pragma unroll
    for (int i = 0; i < 4; ++i) {
        m_i[i] = -1e30f; l_i[i] = 0.f;
        #pragma unroll
        for (int j = 0; j < 4; ++j) acc[i][j] = 0.f;
    }

    for (int j = 0; j <= qb; ++j) {
        __syncthreads();
        for (int i = tid; i < 64*16; i += 256) {
            int r = i >> 4, d4 = (i & 15) << 2;
            const float* rowp = qkv + (size_t)(b*L_ + j*64 + r)*QKV_DIM;
            float4 kv = *(const float4*)(rowp + kcol + d4);
            KP[d4+0][r]=kv.x; KP[d4+1][r]=kv.y; KP[d4+2][r]=kv.z; KP[d4+3][r]=kv.w;
            *(float4*)(&Vs[r][d4]) = *(const float4*)(rowp + vcol + d4);
        }
        __syncthreads();

        float s[4][4];
        #pragma unroll
        for (int i = 0; i < 4; ++i)
            #pragma unroll
            for (int jj = 0; jj < 4; ++jj) s[i][jj] = 0.f;
        #pragma unroll 8
        for (int kk = 0; kk < 64; ++kk) {
            float a[4], bb[4];
            #pragma unroll
            for (int i = 0; i < 4; ++i)  a[i]  = Qt[kk][ty*4+i];
            #pragma unroll
            for (int jj = 0; jj < 4; ++jj) bb[jj] = KP[kk][tx*4+jj];
            #pragma unroll
            for (int i = 0; i < 4; ++i)
                #pragma unroll
                for (int jj = 0; jj < 4; ++jj) s[i][jj] = fmaf(a[i], bb[jj], s[i][jj]);
        }
        const bool diag = (j == qb);
        #pragma unroll
        for (int i = 0; i < 4; ++i)
            #pragma unroll
            for (int jj = 0; jj < 4; ++jj) {
                bool masked = diag && ((tx*4+jj) > (ty*4+i));
                s[i][jj] = masked ? -1e30f : s[i][jj]*0.125f;
            }

        float p[4][4];
        #pragma unroll
        for (int i = 0; i < 4; ++i) {
            float rm = fmaxf(fmaxf(s[i][0], s[i][1]), fmaxf(s[i][2], s[i][3]));
            #pragma unroll
            for (int o = 8; o; o >>= 1) rm = fmaxf(rm, __shfl_xor_sync(0xffffffffu, rm, o));
            float mnew = fmaxf(m_i[i], rm);
            float rs = 0.f;
            #pragma unroll
            for (int jj = 0; jj < 4; ++jj) { p[i][jj] = __expf(s[i][jj] - mnew); rs += p[i][jj]; }
            #pragma unroll
            for (int o = 8; o; o >>= 1) rs += __shfl_xor_sync(0xffffffffu, rs, o);
            float corr = __expf(m_i[i] - mnew);
            l_i[i] = l_i[i]*corr + rs;
            m_i[i] = mnew;
            #pragma unroll
            for (int jj = 0; jj < 4; ++jj) acc[i][jj] *= corr;
        }

        __syncthreads();
        #pragma unroll
        for (int i = 0; i < 4; ++i)
            #pragma unroll
            for (int jj = 0; jj < 4; ++jj) KP[tx*4+jj][ty*4+i] = p[i][jj];
        __syncthreads();

        #pragma unroll 8
        for (int kk = 0; kk < 64; ++kk) {
            float a[4], bb[4];
            #pragma unroll
            for (int i = 0; i < 4; ++i)  a[i]  = KP[kk][ty*4+i];
            #pragma unroll
            for (int jj = 0; jj < 4; ++jj) bb[jj] = Vs[kk][tx*4+jj];
            #pragma unroll
            for (int i = 0; i < 4; ++i)
                #pragma unroll
                for (int jj = 0; jj < 4; ++jj) acc[i][jj] = fmaf(a[i], bb[jj], acc[i][jj]);
        }
    }

    #pragma unroll
    for (int i = 0; i < 4; ++i) {
        float invl = 1.f / l_i[i];
        #pragma unroll
        for (int jj = 0; jj < 4; ++jj)
            ctx[(size_t)(b*L_ + qb*64 + ty*4+i)*HID + h*HD + tx*4 + jj] = acc[i][jj]*invl;
    }
}

// ---------------- depthwise causal conv (MK=4) + mup + bias + SiLU ----------------
__global__ void conv_kernel(const float* __restrict__ proj, const float* __restrict__ cw,
                            const float* __restrict__ cb, float* __restrict__ out)
{
    int idx = blockIdx.x*256 + threadIdx.x;
    if (idx >= MROWS*CONV_DIM) return;
    int c = idx % CONV_DIM;
    int ml = idx / CONV_DIM;
    int l = ml % L_, b = ml / L_;
    float mupf = (c < DSSM) ? 0.9f : ((c < DSSM+MS) ? 0.8f : 1.1f);
    float s = 0.f;
    #pragma unroll
    for (int k = 0; k < MK; ++k) {
        int ls = l + k - (MK-1);
        if (ls >= 0) s += proj[(size_t)(b*L_+ls)*PROJ_DIM + DSSM + c] * cw[c*MK + k];
    }
    s = mupf*s + cb[c];
    out[idx] = siluf(s);
}

// ---------------- Mamba2 selective scan ----------------
#define SCT 32
__global__ __launch_bounds__(256) void scan_kernel(
    const float* __restrict__ conv, const float* __restrict__ proj,
    const float* __restrict__ A_log, const float* __restrict__ dt_bias,
    const float* __restrict__ Dp, float* __restrict__ y)
{
    const int b = blockIdx.x / MH, h = blockIdx.x % MH;
    const int tid = threadIdx.x;
    const int p = tid >> 2, sg = tid & 3, s0 = sg*16;
    const float Ah = -__expf(A_log[h]);
    const float Dh = Dp[h];
    const float dtb = dt_bias[h];
    float st[16];
    #pragma unroll
    for (int i = 0; i < 16; ++i) st[i] = 0.f;

    __shared__ float xs[SCT][64], Bsh[SCT][64], Csh[SCT][64], dts[SCT];

    for (int l0 = 0; l0 < L_; l0 += SCT) {
        __syncthreads();
        for (int i = tid; i < SCT*64; i += 256) {
            int t = i >> 6, c = i & 63;
            size_t base = (size_t)(b*L_ + l0 + t)*CONV_DIM;
            xs[t][c]  = conv[base + h*64 + c];
            Bsh[t][c] = conv[base + DSSM + c];
            Csh[t][c] = conv[base + DSSM + MS + c];
        }
        for (int i = tid; i < SCT; i += 256) {
            float r = proj[(size_t)(b*L_ + l0 + i)*PROJ_DIM + (PROJ_DIM-MH) + h] * 1.2f + dtb;
            dts[i] = (r > 20.f) ? r : log1pf(expf(r));   // softplus
        }
        __syncthreads();
        for (int t = 0; t < SCT; ++t) {
            float dt = dts[t];
            float dA = __expf(dt * Ah);
            float xv = xs[t][p];
            float coef = dt * xv;
            float acc = 0.f;
            #pragma unroll
            for (int ss = 0; ss < 16; ++ss) {
                st[ss] = st[ss]*dA + coef*Bsh[t][s0+ss];
                acc = fmaf(st[ss], Csh[t][s0+ss], acc);
            }
            acc += __shfl_xor_sync(0xffffffffu, acc, 1);
            acc += __shfl_xor_sync(0xffffffffu, acc, 2);
            if (sg == 0)
                y[(size_t)(b*L_ + l0 + t)*DSSM + h*64 + p] = acc + xv*Dh;
        }
    }
}

// ---------------- gating + RMS ----------------
__global__ __launch_bounds__(256) void gate_rms_kernel(
    const float* __restrict__ y, const float* __restrict__ proj,
    const float* __restrict__ w, float* __restrict__ out)
{
    int m = blockIdx.x;
    const float* yr = y + (size_t)m*DSSM;
    const float* zr = proj + (size_t)m*PROJ_DIM;
    float v[8]; float ss = 0.f;
    #pragma unroll
    for (int k = 0; k < 8; ++k) {
        int c = threadIdx.x + k*256;
        float z = zr[c];
        float gv = yr[c] * siluf(z);
        v[k] = gv; ss += gv*gv;
    }
    ss = blockReduceSum256(ss);
    __shared__ float s_inv;
    if (threadIdx.x == 0) s_inv = rsqrtf(ss * (1.f/DSSM) + EPS_);
    __syncthreads();
    float inv = s_inv;
    float* o = out + (size_t)m*DSSM;
    #pragma unroll
    for (int k = 0; k < 8; ++k) { int c = threadIdx.x + k*256; o[c] = v[k]*inv*w[c]; }
}

// ---------------- combine: h = as + residual ; hn = rms(h)*w ----------------
__global__ __launch_bounds__(256) void combine_kernel(
    const float* __restrict__ as_, const float* __restrict__ resid,
    const float* __restrict__ w, float* __restrict__ h, float* __restrict__ hn)
{
    int m = blockIdx.x;
    const float* ar = as_  + (size_t)m*HID;
    const float* rr = resid + (size_t)m*HID;
    float v[8]; float ss = 0.f;
    #pragma unroll
    for (int k = 0; k < 8; ++k) {
        int c = threadIdx.x + k*256;
        float hv = ar[c] + rr[c];
        v[k] = hv; ss += hv*hv;
    }
    ss = blockReduceSum256(ss);
    __shared__ float s_inv;
    if (threadIdx.x == 0) s_inv = rsqrtf(ss * (1.f/HID) + EPS_);
    __syncthreads();
    float inv = s_inv;
    float* ho = h + (size_t)m*HID;
    float* no = hn + (size_t)m*HID;
    #pragma unroll
    for (int k = 0; k < 8; ++k) {
        int c = threadIdx.x + k*256;
        ho[c] = v[k];
        no[c] = v[k]*inv*w[c];
    }
}

// ---------------- SwiGLU activation ----------------
__global__ void act_kernel(const float* __restrict__ gu, float* __restrict__ act) {
    int idx = blockIdx.x*256 + threadIdx.x;
    if (idx >= MROWS*INTER) return;
    int m = idx / INTER, i = idx % INTER;
    const float* row = gu + (size_t)m*(2*INTER);
    float gate = row[i] * GATE_MULT;
    float up   = row[INTER + i];
    act[idx] = siluf(gate) * up;
}

// ---------------- host launcher ----------------
extern "C" void kernel_launch(void* const* d_in, const int* in_sizes, int n_in,
                              void* d_out, int out_size)
{
    const float* hidden      = (const float*)d_in[0];
    const int*   positions   = (const int*)  d_in[1];
    const float* w_in_ln     = (const float*)d_in[2];
    const float* qkv_w       = (const float*)d_in[3];
    const float* o_w         = (const float*)d_in[4];
    const float* in_proj_w   = (const float*)d_in[5];
    const float* conv_w      = (const float*)d_in[6];
    const float* conv_b      = (const float*)d_in[7];
    const float* A_log       = (const float*)d_in[8];
    const float* dt_bias     = (const float*)d_in[9];
    const float* Dp          = (const float*)d_in[10];
    const float* ssm_norm_w  = (const float*)d_in[11];
    const float* out_proj_w  = (const float*)d_in[12];
    const float* w_pre_ff_ln = (const float*)d_in[13];
    const float* gate_up_w   = (const float*)d_in[14];
    const float* down_w      = (const float*)d_in[15];
    float* out = (float*)d_out;

    float *hs, *qkv, *ctx, *proj, *conv, *y, *gt, *as_, *h, *hn, *gu, *act;
    cudaGetSymbolAddress((void**)&hs,  g_hs);
    cudaGetSymbolAddress((void**)&qkv, g_qkv);
    cudaGetSymbolAddress((void**)&ctx, g_ctx);
    cudaGetSymbolAddress((void**)&proj,g_proj);
    cudaGetSymbolAddress((void**)&conv,g_conv);
    cudaGetSymbolAddress((void**)&y,   g_y);
    cudaGetSymbolAddress((void**)&gt,  g_gt);
    cudaGetSymbolAddress((void**)&as_, g_as);
    cudaGetSymbolAddress((void**)&h,   g_h);
    cudaGetSymbolAddress((void**)&hn,  g_hn);
    cudaGetSymbolAddress((void**)&gu,  g_gu);
    cudaGetSymbolAddress((void**)&act, g_act);

    // 1. input RMS norm
    rms_kernel<<<MROWS, 256>>>(hidden, w_in_ln, hs);

    // 2. qkv = (hs*ATTN_IN) @ qkv_w^T   and   proj = (hs*SSM_IN) @ in_proj_w^T
    gemm_tf32<<<dim3(QKV_DIM/TBN, MROWS/TBM), 256>>>(MROWS, QKV_DIM, HID, ATTN_IN,
                                                     hs, qkv_w, 0.f, nullptr, qkv);
    gemm_tf32<<<dim3((PROJ_DIM+TBN-1)/TBN, MROWS/TBM), 256>>>(MROWS, PROJ_DIM, HID, SSM_IN,
                                                     hs, in_proj_w, 0.f, nullptr, proj);

    // 3. RoPE (q; k scaled by KEY_MULT)
    rope_kernel<<<(MROWS*(NH+NKV)*32 + 255)/256, 256>>>(qkv, positions);

    // 4. attention
    attn_kernel<<<dim3(L_/64, NH, B_), 256>>>(qkv, ctx);

    // 5. as = ATTN_OUT * ctx @ o_w^T
    gemm_tf32<<<dim3(HID/TBN, MROWS/TBM), 256>>>(MROWS, HID, HID, ATTN_OUT,
                                                 ctx, o_w, 0.f, nullptr, as_);

    // 6. mamba: conv -> scan -> gate+rms -> out_proj (accumulated into as)
    conv_kernel<<<(MROWS*CONV_DIM + 255)/256, 256>>>(proj, conv_w, conv_b, conv);
    scan_kernel<<<B_*MH, 256>>>(conv, proj, A_log, dt_bias, Dp, y);
    gate_rms_kernel<<<MROWS, 256>>>(y, proj, ssm_norm_w, gt);
    gemm_tf32<<<dim3(HID/TBN, MROWS/TBM), 256>>>(MROWS, HID, DSSM, SSM_OUT,
                                                 gt, out_proj_w, 1.f, as_, as_);

    // 7. combine + pre-FF RMS
    combine_kernel<<<MROWS, 256>>>(as_, hidden, w_pre_ff_ln, h, hn);

    // 8. MLP
    gemm_tf32<<<dim3(2*INTER/TBN, MROWS/TBM), 256>>>(MROWS, 2*INTER, HID, 1.f,
                                                     hn, gate_up_w, 0.f, nullptr, gu);
    act_kernel<<<(MROWS*INTER + 255)/256, 256>>>(gu, act);
    gemm_tf32<<<dim3(HID/TBN, MROWS/TBM), 256>>>(MROWS, HID, INTER, DOWN_MULT,
                                                 act, down_w, 1.f, h, out);
    (void)in_sizes; (void)n_in; (void)out_size;
}

// round 5
// speedup vs baseline: 2.6668x; 1.1479x over previous
#include <cuda_runtime.h>
#include <math.h>
#include <stdint.h>

#define B_ 2
#define L_ 1024
#define HID 2048
#define NH 32
#define HD 64
#define NKV 8
#define INTER 8192
#define DSSM 2048
#define MH 32
#define MP 64
#define MS 64
#define MK 4
#define CONV_DIM (DSSM + 2*MS)          // 2176
#define PROJ_DIM (2*DSSM + 2*MS + MH)   // 4256
#define QKV_DIM (NH*HD + 2*NKV*HD)      // 3072
#define MROWS (B_*L_)                   // 2048

#define ATTN_IN 1.2f
#define ATTN_OUT 0.8f
#define KEY_MULT 0.7f
#define SSM_IN 1.1f
#define SSM_OUT 0.9f
#define GATE_MULT 0.9f
#define DOWN_MULT 0.8f
#define EPS_ 1e-5f

// ---------------- scratch (device globals; no allocation allowed) ----------------
__device__ float g_hs  [MROWS*HID];
__device__ float g_qkv [MROWS*QKV_DIM];
__device__ float g_ctx [MROWS*HID];
__device__ float g_proj[MROWS*PROJ_DIM];
__device__ float g_conv[MROWS*CONV_DIM];
__device__ float g_y   [MROWS*DSSM];
__device__ float g_gt  [MROWS*DSSM];
__device__ float g_as  [MROWS*HID];
__device__ float g_h   [MROWS*HID];
__device__ float g_hn  [MROWS*HID];
__device__ float g_gu  [(size_t)MROWS*2*INTER];
__device__ float g_act [(size_t)MROWS*INTER];

// ---------------- helpers ----------------
__device__ __forceinline__ float blockReduceSum256(float v) {
    __shared__ float sh[8];
    int lane = threadIdx.x & 31, w = threadIdx.x >> 5;
    #pragma unroll
    for (int o = 16; o; o >>= 1) v += __shfl_xor_sync(0xffffffffu, v, o);
    if (lane == 0) sh[w] = v;
    __syncthreads();
    v = (threadIdx.x < 8) ? sh[threadIdx.x] : 0.f;
    if (w == 0) {
        #pragma unroll
        for (int o = 4; o; o >>= 1) v += __shfl_xor_sync(0xffu, v, o);
    }
    return v;   // valid on thread 0
}

__device__ __forceinline__ float siluf(float x) { return x / (1.f + __expf(-x)); }

__device__ __forceinline__ uint32_t f2tf32(float f) {
    uint32_t u; asm("cvt.rna.tf32.f32 %0, %1;" : "=r"(u) : "f"(f)); return u;
}

__device__ __forceinline__ void mma_tf32(float* c, const uint32_t* a, const uint32_t* b) {
    asm volatile(
        "mma.sync.aligned.m16n8k8.row.col.f32.tf32.tf32.f32 "
        "{%0,%1,%2,%3}, {%4,%5,%6,%7}, {%8,%9}, {%0,%1,%2,%3};"
        : "+f"(c[0]), "+f"(c[1]), "+f"(c[2]), "+f"(c[3])
        : "r"(a[0]), "r"(a[1]), "r"(a[2]), "r"(a[3]), "r"(b[0]), "r"(b[1]));
}

__device__ __forceinline__ uint32_t smem_u32(const void* p) {
    uint32_t a;
    asm("{ .reg .u64 t; cvta.to.shared.u64 t, %1; cvt.u32.u64 %0, t; }" : "=r"(a) : "l"(p));
    return a;
}
__device__ __forceinline__ void cp_async16(uint32_t dst, const void* src, int srcBytes) {
    asm volatile("cp.async.cg.shared.global [%0], [%1], 16, %2;"
                 :: "r"(dst), "l"(src), "r"(srcBytes));
}
#define CP_COMMIT() asm volatile("cp.async.commit_group;" ::: "memory")
#define CP_WAIT1()  asm volatile("cp.async.wait_group 1;"  ::: "memory")

// ---------------- TF32 tensor-core GEMM v2 ----------------
// C = alpha * A(MxK) @ B(NxK)^T + beta * Cin.
// 128x128x32 tile, 8 warps (2x4), warp tile 64x32, m16n8k8.
// cp.async double-buffered raw-fp32 smem (stride 36 -> conflict-free),
// tf32 conversion in the fragment-load path. 2 CTAs/SM.
#define TBM 128
#define TBN 128
#define TBK 32
#define TST 36
#define STG (128*TST)                 // floats per matrix per stage
#define GSMEM_BYTES (4*STG*4)         // As0,Bs0,As1,Bs1 = 73728 B

__global__ __launch_bounds__(256, 2) void gemm_tf32(
    int Mi, int Ni, int Ki, float alpha,
    const float* __restrict__ A, const float* __restrict__ Bw,
    float beta, const float* __restrict__ Cin, float* __restrict__ C)
{
    extern __shared__ float sm[];
    float* As[2] = { sm,         sm + 2*STG };
    float* Bs[2] = { sm + STG,   sm + 3*STG };

    const int tid = threadIdx.x;
    const int bm = blockIdx.y * TBM, bn = blockIdx.x * TBN;
    const int warp = tid >> 5, lane = tid & 31;
    const int g = lane >> 2, t = lane & 3;
    const int wm = (warp >> 2) * 64;
    const int wn = (warp & 3) * 32;

    // load assignment: chunk = q*256+tid (0..1023); row=chunk>>3; c16=chunk&7
    const int lrow = tid >> 3;          // base row (stride 32 across q)
    const int lc16 = tid & 7;           // 16B column chunk

    const int nk = Ki / TBK;

    // ---- prologue: stage 0 ----
    {
        const int k0 = 0;
        #pragma unroll
        for (int q = 0; q < 4; ++q) {
            int row = lrow + q*32;
            uint32_t dA = smem_u32(As[0] + row*TST + lc16*4);
            cp_async16(dA, A + (size_t)(bm + row)*Ki + k0 + lc16*4, 16);
            int brow = bn + row;
            uint32_t dB = smem_u32(Bs[0] + row*TST + lc16*4);
            const float* srcB = Bw + (size_t)(brow < Ni ? brow : 0)*Ki + k0 + lc16*4;
            cp_async16(dB, srcB, brow < Ni ? 16 : 0);
        }
        CP_COMMIT();
    }

    float acc[4][4][4];
    #pragma unroll
    for (int i = 0; i < 4; ++i)
        #pragma unroll
        for (int j = 0; j < 4; ++j)
            #pragma unroll
            for (int r = 0; r < 4; ++r) acc[i][j][r] = 0.f;

    for (int j = 0; j < nk; ++j) {
        const int b = j & 1;
        // issue next stage loads
        if (j + 1 < nk) {
            const int k0 = (j + 1) * TBK;
            const int nb = b ^ 1;
            #pragma unroll
            for (int q = 0; q < 4; ++q) {
                int row = lrow + q*32;
                uint32_t dA = smem_u32(As[nb] + row*TST + lc16*4);
                cp_async16(dA, A + (size_t)(bm + row)*Ki + k0 + lc16*4, 16);
                int brow = bn + row;
                uint32_t dB = smem_u32(Bs[nb] + row*TST + lc16*4);
                const float* srcB = Bw + (size_t)(brow < Ni ? brow : 0)*Ki + k0 + lc16*4;
                cp_async16(dB, srcB, brow < Ni ? 16 : 0);
            }
        }
        CP_COMMIT();
        CP_WAIT1();
        __syncthreads();

        const float* as = As[b];
        const float* bs = Bs[b];
        #pragma unroll
        for (int ks = 0; ks < 4; ++ks) {
            uint32_t af[4][4];
            #pragma unroll
            for (int i = 0; i < 4; ++i) {
                const float* base = as + (wm + i*16 + g)*TST + ks*8 + t;
                af[i][0] = f2tf32(base[0]);
                af[i][1] = f2tf32(base[8*TST]);
                af[i][2] = f2tf32(base[4]);
                af[i][3] = f2tf32(base[8*TST + 4]);
            }
            uint32_t bf[4][2];
            #pragma unroll
            for (int jj = 0; jj < 4; ++jj) {
                const float* base = bs + (wn + jj*8 + g)*TST + ks*8 + t;
                bf[jj][0] = f2tf32(base[0]);
                bf[jj][1] = f2tf32(base[4]);
            }
            #pragma unroll
            for (int i = 0; i < 4; ++i)
                #pragma unroll
                for (int jj = 0; jj < 4; ++jj)
                    mma_tf32(acc[i][jj], af[i], bf[jj]);
        }
        __syncthreads();
    }

    // epilogue: c0 (g,2t) c1 (g,2t+1) c2 (g+8,2t) c3 (g+8,2t+1)
    #pragma unroll
    for (int i = 0; i < 4; ++i) {
        int row0 = bm + wm + i*16 + g;
        #pragma unroll
        for (int j = 0; j < 4; ++j) {
            int col = bn + wn + j*8 + 2*t;
            if (col >= Ni) continue;
            size_t o0 = (size_t)row0 * Ni + col;
            size_t o1 = (size_t)(row0 + 8) * Ni + col;
            float2 v0 = make_float2(alpha*acc[i][j][0], alpha*acc[i][j][1]);
            float2 v1 = make_float2(alpha*acc[i][j][2], alpha*acc[i][j][3]);
            if (beta != 0.f) {
                float2 e0 = *(const float2*)(Cin + o0);
                float2 e1 = *(const float2*)(Cin + o1);
                v0.x += beta*e0.x; v0.y += beta*e0.y;
                v1.x += beta*e1.x; v1.y += beta*e1.y;
            }
            *(float2*)(C + o0) = v0;
            *(float2*)(C + o1) = v1;
        }
    }
}

// ---------------- RMS norm: out = rms(x)*w ----------------
__global__ __launch_bounds__(256) void rms_kernel(
    const float* __restrict__ x, const float* __restrict__ w, float* __restrict__ out)
{
    int m = blockIdx.x;
    const float* xr = x + (size_t)m * HID;
    float v[8]; float ss = 0.f;
    #pragma unroll
    for (int k = 0; k < 8; ++k) { v[k] = xr[threadIdx.x + k*256]; ss += v[k]*v[k]; }
    ss = blockReduceSum256(ss);
    __shared__ float s_inv;
    if (threadIdx.x == 0) s_inv = rsqrtf(ss * (1.f/HID) + EPS_);
    __syncthreads();
    float inv = s_inv;
    float* o = out + (size_t)m * HID;
    #pragma unroll
    for (int k = 0; k < 8; ++k) { int c = threadIdx.x + k*256; o[c] = v[k]*inv*w[c]; }
}

// ---------------- RoPE in place on qkv ----------------
__global__ void rope_kernel(float* __restrict__ qkv, const int* __restrict__ positions) {
    int idx = blockIdx.x*256 + threadIdx.x;
    const int total = MROWS*(NH+NKV)*32;
    if (idx >= total) return;
    int i = idx & 31; int rest = idx >> 5;
    int head = rest % (NH+NKV); int ml = rest / (NH+NKV);
    int l = ml % L_;
    int col; float mult;
    if (head < NH) { col = head*HD; mult = 1.f; }
    else           { col = NH*HD + (head-NH)*HD; mult = KEY_MULT; }
    float* p = qkv + (size_t)ml*QKV_DIM + col;
    float inv = powf(1e11f, -(float)i/32.0f);
    float ang = (float)positions[l] * inv;
    float c = cosf(ang), s = sinf(ang);
    float x1 = p[i]*mult, x2 = p[i+32]*mult;
    p[i]    = x1*c - x2*s;
    p[i+32] = x2*c + x1*s;
}

// ---------------- Flash attention (causal, GQA 32q/8kv, HD=64) ----------------
__global__ __launch_bounds__(256) void attn_kernel(
    const float* __restrict__ qkv, float* __restrict__ ctx)
{
    __shared__ float Qt[64][64];
    __shared__ float KP[64][64];
    __shared__ float Vs[64][64];
    const int tid = threadIdx.x;
    const int ty = tid >> 4, tx = tid & 15;
    const int qb = blockIdx.x, h = blockIdx.y, b = blockIdx.z;
    const int g = h >> 2;
    const int qcol = h*HD;
    const int kcol = NH*HD + g*HD;
    const int vcol = NH*HD + NKV*HD + g*HD;

    for (int i = tid; i < 64*16; i += 256) {
        int r = i >> 4, d4 = (i & 15) << 2;
        float4 v = *(const float4*)(qkv + (size_t)(b*L_ + qb*64 + r)*QKV_DIM + qcol + d4);
        Qt[d4+0][r]=v.x; Qt[d4+1][r]=v.y; Qt[d4+2][r]=v.z; Qt[d4+3][r]=v.w;
    }

    float acc[4][4]; float m_i[4], l_i[4];
    #pragma unroll
    for (int i = 0; i < 4; ++i) {
        m_i[i] = -1e30f; l_i[i] = 0.f;
        #pragma unroll
        for (int j = 0; j < 4; ++j) acc[i][j] = 0.f;
    }

    for (int j = 0; j <= qb; ++j) {
        __syncthreads();
        for (int i = tid; i < 64*16; i += 256) {
            int r = i >> 4, d4 = (i & 15) << 2;
            const float* rowp = qkv + (size_t)(b*L_ + j*64 + r)*QKV_DIM;
            float4 kv = *(const float4*)(rowp + kcol + d4);
            KP[d4+0][r]=kv.x; KP[d4+1][r]=kv.y; KP[d4+2][r]=kv.z; KP[d4+3][r]=kv.w;
            *(float4*)(&Vs[r][d4]) = *(const float4*)(rowp + vcol + d4);
        }
        __syncthreads();

        float s[4][4];
        #pragma unroll
        for (int i = 0; i < 4; ++i)
            #pragma unroll
            for (int jj = 0; jj < 4; ++jj) s[i][jj] = 0.f;
        #pragma unroll 8
        for (int kk = 0; kk < 64; ++kk) {
            float a[4], bb[4];
            #pragma unroll
            for (int i = 0; i < 4; ++i)  a[i]  = Qt[kk][ty*4+i];
            #pragma unroll
            for (int jj = 0; jj < 4; ++jj) bb[jj] = KP[kk][tx*4+jj];
            #pragma unroll
            for (int i = 0; i < 4; ++i)
                #pragma unroll
                for (int jj = 0; jj < 4; ++jj) s[i][jj] = fmaf(a[i], bb[jj], s[i][jj]);
        }
        const bool diag = (j == qb);
        #pragma unroll
        for (int i = 0; i < 4; ++i)
            #pragma unroll
            for (int jj = 0; jj < 4; ++jj) {
                bool masked = diag && ((tx*4+jj) > (ty*4+i));
                s[i][jj] = masked ? -1e30f : s[i][jj]*0.125f;
            }

        float p[4][4];
        #pragma unroll
        for (int i = 0; i < 4; ++i) {
            float rm = fmaxf(fmaxf(s[i][0], s[i][1]), fmaxf(s[i][2], s[i][3]));
            #pragma unroll
            for (int o = 8; o; o >>= 1) rm = fmaxf(rm, __shfl_xor_sync(0xffffffffu, rm, o));
            float mnew = fmaxf(m_i[i], rm);
            float rs = 0.f;
            #pragma unroll
            for (int jj = 0; jj < 4; ++jj) { p[i][jj] = __expf(s[i][jj] - mnew); rs += p[i][jj]; }
            #pragma unroll
            for (int o = 8; o; o >>= 1) rs += __shfl_xor_sync(0xffffffffu, rs, o);
            float corr = __expf(m_i[i] - mnew);
            l_i[i] = l_i[i]*corr + rs;
            m_i[i] = mnew;
            #pragma unroll
            for (int jj = 0; jj < 4; ++jj) acc[i][jj] *= corr;
        }

        __syncthreads();
        #pragma unroll
        for (int i = 0; i < 4; ++i)
            #pragma unroll
            for (int jj = 0; jj < 4; ++jj) KP[tx*4+jj][ty*4+i] = p[i][jj];
        __syncthreads();

        #pragma unroll 8
        for (int kk = 0; kk < 64; ++kk) {
            float a[4], bb[4];
            #pragma unroll
            for (int i = 0; i < 4; ++i)  a[i]  = KP[kk][ty*4+i];
            #pragma unroll
            for (int jj = 0; jj < 4; ++jj) bb[jj] = Vs[kk][tx*4+jj];
            #pragma unroll
            for (int i = 0; i < 4; ++i)
                #pragma unroll
                for (int jj = 0; jj < 4; ++jj) acc[i][jj] = fmaf(a[i], bb[jj], acc[i][jj]);
        }
    }

    #pragma unroll
    for (int i = 0; i < 4; ++i) {
        float invl = 1.f / l_i[i];
        #pragma unroll
        for (int jj = 0; jj < 4; ++jj)
            ctx[(size_t)(b*L_ + qb*64 + ty*4+i)*HID + h*HD + tx*4 + jj] = acc[i][jj]*invl;
    }
}

// ---------------- depthwise causal conv (MK=4) + mup + bias + SiLU ----------------
__global__ void conv_kernel(const float* __restrict__ proj, const float* __restrict__ cw,
                            const float* __restrict__ cb, float* __restrict__ out)
{
    int idx = blockIdx.x*256 + threadIdx.x;
    if (idx >= MROWS*CONV_DIM) return;
    int c = idx % CONV_DIM;
    int ml = idx / CONV_DIM;
    int l = ml % L_, b = ml / L_;
    float mupf = (c < DSSM) ? 0.9f : ((c < DSSM+MS) ? 0.8f : 1.1f);
    float s = 0.f;
    #pragma unroll
    for (int k = 0; k < MK; ++k) {
        int ls = l + k - (MK-1);
        if (ls >= 0) s += proj[(size_t)(b*L_+ls)*PROJ_DIM + DSSM + c] * cw[c*MK + k];
    }
    s = mupf*s + cb[c];
    out[idx] = siluf(s);
}

// ---------------- Mamba2 selective scan ----------------
#define SCT 32
__global__ __launch_bounds__(256) void scan_kernel(
    const float* __restrict__ conv, const float* __restrict__ proj,
    const float* __restrict__ A_log, const float* __restrict__ dt_bias,
    const float* __restrict__ Dp, float* __restrict__ y)
{
    const int b = blockIdx.x / MH, h = blockIdx.x % MH;
    const int tid = threadIdx.x;
    const int p = tid >> 2, sg = tid & 3, s0 = sg*16;
    const float Ah = -__expf(A_log[h]);
    const float Dh = Dp[h];
    const float dtb = dt_bias[h];
    float st[16];
    #pragma unroll
    for (int i = 0; i < 16; ++i) st[i] = 0.f;

    __shared__ float xs[SCT][64], Bsh[SCT][64], Csh[SCT][64], dts[SCT];

    for (int l0 = 0; l0 < L_; l0 += SCT) {
        __syncthreads();
        for (int i = tid; i < SCT*64; i += 256) {
            int t = i >> 6, c = i & 63;
            size_t base = (size_t)(b*L_ + l0 + t)*CONV_DIM;
            xs[t][c]  = conv[base + h*64 + c];
            Bsh[t][c] = conv[base + DSSM + c];
            Csh[t][c] = conv[base + DSSM + MS + c];
        }
        for (int i = tid; i < SCT; i += 256) {
            float r = proj[(size_t)(b*L_ + l0 + i)*PROJ_DIM + (PROJ_DIM-MH) + h] * 1.2f + dtb;
            dts[i] = (r > 20.f) ? r : log1pf(expf(r));   // softplus
        }
        __syncthreads();
        for (int t = 0; t < SCT; ++t) {
            float dt = dts[t];
            float dA = __expf(dt * Ah);
            float xv = xs[t][p];
            float coef = dt * xv;
            float acc = 0.f;
            #pragma unroll
            for (int ss = 0; ss < 16; ++ss) {
                st[ss] = st[ss]*dA + coef*Bsh[t][s0+ss];
                acc = fmaf(st[ss], Csh[t][s0+ss], acc);
            }
            acc += __shfl_xor_sync(0xffffffffu, acc, 1);
            acc += __shfl_xor_sync(0xffffffffu, acc, 2);
            if (sg == 0)
                y[(size_t)(b*L_ + l0 + t)*DSSM + h*64 + p] = acc + xv*Dh;
        }
    }
}

// ---------------- gating + RMS ----------------
__global__ __launch_bounds__(256) void gate_rms_kernel(
    const float* __restrict__ y, const float* __restrict__ proj,
    const float* __restrict__ w, float* __restrict__ out)
{
    int m = blockIdx.x;
    const float* yr = y + (size_t)m*DSSM;
    const float* zr = proj + (size_t)m*PROJ_DIM;
    float v[8]; float ss = 0.f;
    #pragma unroll
    for (int k = 0; k < 8; ++k) {
        int c = threadIdx.x + k*256;
        float z = zr[c];
        float gv = yr[c] * siluf(z);
        v[k] = gv; ss += gv*gv;
    }
    ss = blockReduceSum256(ss);
    __shared__ float s_inv;
    if (threadIdx.x == 0) s_inv = rsqrtf(ss * (1.f/DSSM) + EPS_);
    __syncthreads();
    float inv = s_inv;
    float* o = out + (size_t)m*DSSM;
    #pragma unroll
    for (int k = 0; k < 8; ++k) { int c = threadIdx.x + k*256; o[c] = v[k]*inv*w[c]; }
}

// ---------------- combine: h = as + residual ; hn = rms(h)*w ----------------
__global__ __launch_bounds__(256) void combine_kernel(
    const float* __restrict__ as_, const float* __restrict__ resid,
    const float* __restrict__ w, float* __restrict__ h, float* __restrict__ hn)
{
    int m = blockIdx.x;
    const float* ar = as_  + (size_t)m*HID;
    const float* rr = resid + (size_t)m*HID;
    float v[8]; float ss = 0.f;
    #pragma unroll
    for (int k = 0; k < 8; ++k) {
        int c = threadIdx.x + k*256;
        float hv = ar[c] + rr[c];
        v[k] = hv; ss += hv*hv;
    }
    ss = blockReduceSum256(ss);
    __shared__ float s_inv;
    if (threadIdx.x == 0) s_inv = rsqrtf(ss * (1.f/HID) + EPS_);
    __syncthreads();
    float inv = s_inv;
    float* ho = h + (size_t)m*HID;
    float* no = hn + (size_t)m*HID;
    #pragma unroll
    for (int k = 0; k < 8; ++k) {
        int c = threadIdx.x + k*256;
        ho[c] = v[k];
        no[c] = v[k]*inv*w[c];
    }
}

// ---------------- SwiGLU activation ----------------
__global__ void act_kernel(const float* __restrict__ gu, float* __restrict__ act) {
    int idx = blockIdx.x*256 + threadIdx.x;
    if (idx >= MROWS*INTER) return;
    int m = idx / INTER, i = idx % INTER;
    const float* row = gu + (size_t)m*(2*INTER);
    float gate = row[i] * GATE_MULT;
    float up   = row[INTER + i];
    act[idx] = siluf(gate) * up;
}

// ---------------- host launcher ----------------
extern "C" void kernel_launch(void* const* d_in, const int* in_sizes, int n_in,
                              void* d_out, int out_size)
{
    const float* hidden      = (const float*)d_in[0];
    const int*   positions   = (const int*)  d_in[1];
    const float* w_in_ln     = (const float*)d_in[2];
    const float* qkv_w       = (const float*)d_in[3];
    const float* o_w         = (const float*)d_in[4];
    const float* in_proj_w   = (const float*)d_in[5];
    const float* conv_w      = (const float*)d_in[6];
    const float* conv_b      = (const float*)d_in[7];
    const float* A_log       = (const float*)d_in[8];
    const float* dt_bias     = (const float*)d_in[9];
    const float* Dp          = (const float*)d_in[10];
    const float* ssm_norm_w  = (const float*)d_in[11];
    const float* out_proj_w  = (const float*)d_in[12];
    const float* w_pre_ff_ln = (const float*)d_in[13];
    const float* gate_up_w   = (const float*)d_in[14];
    const float* down_w      = (const float*)d_in[15];
    float* out = (float*)d_out;

    float *hs, *qkv, *ctx, *proj, *conv, *y, *gt, *as_, *h, *hn, *gu, *act;
    cudaGetSymbolAddress((void**)&hs,  g_hs);
    cudaGetSymbolAddress((void**)&qkv, g_qkv);
    cudaGetSymbolAddress((void**)&ctx, g_ctx);
    cudaGetSymbolAddress((void**)&proj,g_proj);
    cudaGetSymbolAddress((void**)&conv,g_conv);
    cudaGetSymbolAddress((void**)&y,   g_y);
    cudaGetSymbolAddress((void**)&gt,  g_gt);
    cudaGetSymbolAddress((void**)&as_, g_as);
    cudaGetSymbolAddress((void**)&h,   g_h);
    cudaGetSymbolAddress((void**)&hn,  g_hn);
    cudaGetSymbolAddress((void**)&gu,  g_gu);
    cudaGetSymbolAddress((void**)&act, g_act);

    cudaFuncSetAttribute(gemm_tf32, cudaFuncAttributeMaxDynamicSharedMemorySize, GSMEM_BYTES);

    const int MT = MROWS/TBM;   // 16

    // 1. input RMS norm
    rms_kernel<<<MROWS, 256>>>(hidden, w_in_ln, hs);

    // 2. qkv = (hs*ATTN_IN) @ qkv_w^T ; proj = (hs*SSM_IN) @ in_proj_w^T
    gemm_tf32<<<dim3(QKV_DIM/TBN, MT), 256, GSMEM_BYTES>>>(MROWS, QKV_DIM, HID, ATTN_IN,
                                                           hs, qkv_w, 0.f, nullptr, qkv);
    gemm_tf32<<<dim3((PROJ_DIM+TBN-1)/TBN, MT), 256, GSMEM_BYTES>>>(MROWS, PROJ_DIM, HID, SSM_IN,
                                                           hs, in_proj_w, 0.f, nullptr, proj);

    // 3. RoPE
    rope_kernel<<<(MROWS*(NH+NKV)*32 + 255)/256, 256>>>(qkv, positions);

    // 4. attention
    attn_kernel<<<dim3(L_/64, NH, B_), 256>>>(qkv, ctx);

    // 5. as = ATTN_OUT * ctx @ o_w^T
    gemm_tf32<<<dim3(HID/TBN, MT), 256, GSMEM_BYTES>>>(MROWS, HID, HID, ATTN_OUT,
                                                       ctx, o_w, 0.f, nullptr, as_);

    // 6. mamba
    conv_kernel<<<(MROWS*CONV_DIM + 255)/256, 256>>>(proj, conv_w, conv_b, conv);
    scan_kernel<<<B_*MH, 256>>>(conv, proj, A_log, dt_bias, Dp, y);
    gate_rms_kernel<<<MROWS, 256>>>(y, proj, ssm_norm_w, gt);
    gemm_tf32<<<dim3(HID/TBN, MT), 256, GSMEM_BYTES>>>(MROWS, HID, DSSM, SSM_OUT,
                                                       gt, out_proj_w, 1.f, as_, as_);

    // 7. combine + pre-FF RMS
    combine_kernel<<<MROWS, 256>>>(as_, hidden, w_pre_ff_ln, h, hn);

    // 8. MLP
    gemm_tf32<<<dim3(2*INTER/TBN, MT), 256, GSMEM_BYTES>>>(MROWS, 2*INTER, HID, 1.f,
                                                           hn, gate_up_w, 0.f, nullptr, gu);
    act_kernel<<<(MROWS*INTER + 255)/256, 256>>>(gu, act);
    gemm_tf32<<<dim3(HID/TBN, MT), 256, GSMEM_BYTES>>>(MROWS, HID, INTER, DOWN_MULT,
                                                       act, down_w, 1.f, h, out);
    (void)in_sizes; (void)n_in; (void)out_size;
}

// round 6
// speedup vs baseline: 4.1592x; 1.5596x over previous
#include <cuda_runtime.h>
#include <cuda_fp16.h>
#include <math.h>
#include <stdint.h>

#define B_ 2
#define L_ 1024
#define HID 2048
#define NH 32
#define HD 64
#define NKV 8
#define INTER 8192
#define DSSM 2048
#define MH 32
#define MP 64
#define MS 64
#define MK 4
#define CONV_DIM (DSSM + 2*MS)          // 2176
#define PROJ_DIM (2*DSSM + 2*MS + MH)   // 4256
#define QKV_DIM (NH*HD + 2*NKV*HD)      // 3072
#define MROWS (B_*L_)                   // 2048

#define ATTN_IN 1.2f
#define ATTN_OUT 0.8f
#define KEY_MULT 0.7f
#define SSM_IN 1.1f
#define SSM_OUT 0.9f
#define GATE_MULT 0.9f
#define DOWN_MULT 0.8f
#define EPS_ 1e-5f

// ---------------- scratch (device globals; no allocation allowed) ----------------
__device__ float  g_qkv [MROWS*QKV_DIM];
__device__ float  g_proj[MROWS*PROJ_DIM];
__device__ float  g_conv[MROWS*CONV_DIM];
__device__ float  g_y   [MROWS*DSSM];
__device__ float  g_as  [MROWS*HID];
__device__ float  g_h   [MROWS*HID];
__device__ float  g_gu  [(size_t)MROWS*2*INTER];

__device__ __half g_hs16 [MROWS*HID];
__device__ __half g_ctx16[MROWS*HID];
__device__ __half g_gt16 [MROWS*DSSM];
__device__ __half g_hn16 [MROWS*HID];
__device__ __half g_act16[(size_t)MROWS*INTER];

// fp16 weights, one big buffer
#define W16_QKV     0
#define W16_INPROJ  (W16_QKV    + QKV_DIM*HID)       // 6291456
#define W16_O       (W16_INPROJ + PROJ_DIM*HID)      // 15007744
#define W16_OUTPROJ (W16_O      + HID*HID)           // 19202048
#define W16_GATEUP  (W16_OUTPROJ+ HID*DSSM)          // 23396352
#define W16_DOWN    (W16_GATEUP + 2*INTER*HID)       // 56950784
#define W16_TOTAL   (W16_DOWN   + HID*INTER)         // 73728000
__device__ __half g_w16[W16_TOTAL];

// ---------------- helpers ----------------
__device__ __forceinline__ float blockReduceSum256(float v) {
    __shared__ float sh[8];
    int lane = threadIdx.x & 31, w = threadIdx.x >> 5;
    #pragma unroll
    for (int o = 16; o; o >>= 1) v += __shfl_xor_sync(0xffffffffu, v, o);
    if (lane == 0) sh[w] = v;
    __syncthreads();
    v = (threadIdx.x < 8) ? sh[threadIdx.x] : 0.f;
    if (w == 0) {
        #pragma unroll
        for (int o = 4; o; o >>= 1) v += __shfl_xor_sync(0xffu, v, o);
    }
    return v;   // valid on thread 0
}

__device__ __forceinline__ float siluf(float x) { return x / (1.f + __expf(-x)); }

__device__ __forceinline__ void mma_f16(float* c, const uint32_t* a, const uint32_t* b) {
    asm volatile(
        "mma.sync.aligned.m16n8k16.row.col.f32.f16.f16.f32 "
        "{%0,%1,%2,%3}, {%4,%5,%6,%7}, {%8,%9}, {%0,%1,%2,%3};"
        : "+f"(c[0]), "+f"(c[1]), "+f"(c[2]), "+f"(c[3])
        : "r"(a[0]), "r"(a[1]), "r"(a[2]), "r"(a[3]), "r"(b[0]), "r"(b[1]));
}

__device__ __forceinline__ uint32_t smem_u32(const void* p) {
    uint32_t a;
    asm("{ .reg .u64 t; cvta.to.shared.u64 t, %1; cvt.u32.u64 %0, t; }" : "=r"(a) : "l"(p));
    return a;
}
__device__ __forceinline__ void cp_async16(uint32_t dst, const void* src, int srcBytes) {
    asm volatile("cp.async.cg.shared.global [%0], [%1], 16, %2;"
                 :: "r"(dst), "l"(src), "r"(srcBytes));
}
#define CP_COMMIT() asm volatile("cp.async.commit_group;" ::: "memory")
#define CP_WAIT1()  asm volatile("cp.async.wait_group 1;"  ::: "memory")

// ---------------- fp32 -> fp16 weight convert ----------------
__global__ void cvt_f16_kernel(const float* __restrict__ in, __half* __restrict__ out, int n4) {
    int i = blockIdx.x*256 + threadIdx.x;
    if (i >= n4) return;
    float4 v = *(const float4*)(in + (size_t)i*4);
    __half2 a = __floats2half2_rn(v.x, v.y);
    __half2 b = __floats2half2_rn(v.z, v.w);
    *(uint2*)(out + (size_t)i*4) = make_uint2(*(uint32_t*)&a, *(uint32_t*)&b);
}

// ---------------- FP16 tensor-core GEMM ----------------
// C(2048xN) = alpha * A(MxK,f16) @ B(NxK,f16)^T + beta * Cin.   fp32 accum/output.
// 128x128x64 tile, 8 warps (2x4), warp tile 64x32, m16n8k16.
// smem: fp16 pairs (b32), row = 32 pairs data + pad -> stride 36 pairs: banks
// (g*36+t) mod 32 all-distinct => conflict-free fragment loads.
#define TBM 128
#define TBN 128
#define TBK 64
#define TSTP 36
#define STGP (128*TSTP)                  // b32 pairs per matrix per stage
#define GSMEM_BYTES (4*STGP*4)           // 73728 B

__global__ __launch_bounds__(256, 2) void gemm_f16(
    int Ni, int Ki, float alpha,
    const __half* __restrict__ A, const __half* __restrict__ Bw,
    float beta, const float* __restrict__ Cin, float* __restrict__ C)
{
    extern __shared__ uint32_t smp[];
    uint32_t* As[2] = { smp,          smp + 2*STGP };
    uint32_t* Bs[2] = { smp + STGP,   smp + 3*STGP };

    const int tid = threadIdx.x;
    const int bm = blockIdx.y * TBM, bn = blockIdx.x * TBN;
    const int warp = tid >> 5, lane = tid & 31;
    const int g = lane >> 2, t = lane & 3;
    const int wm = (warp >> 2) * 64;
    const int wn = (warp & 3) * 32;

    // loads: 128 rows x 8 chunks(16B = 8 halves) per matrix = 1024; 256 thr -> 4 q
    const int lrow = tid >> 3;           // +q*32
    const int lch  = tid & 7;            // 16B chunk (8 halves)

    const int nk = Ki / TBK;

    {   // prologue stage 0
        #pragma unroll
        for (int q = 0; q < 4; ++q) {
            int row = lrow + q*32;
            cp_async16(smem_u32(As[0] + row*TSTP + lch*4),
                       A + (size_t)(bm + row)*Ki + lch*8, 16);
            int brow = bn + row;
            const __half* srcB = Bw + (size_t)(brow < Ni ? brow : 0)*Ki + lch*8;
            cp_async16(smem_u32(Bs[0] + row*TSTP + lch*4), srcB, brow < Ni ? 16 : 0);
        }
        CP_COMMIT();
    }

    float acc[4][4][4];
    #pragma unroll
    for (int i = 0; i < 4; ++i)
        #pragma unroll
        for (int j = 0; j < 4; ++j)
            #pragma unroll
            for (int r = 0; r < 4; ++r) acc[i][j][r] = 0.f;

    for (int j = 0; j < nk; ++j) {
        const int b = j & 1;
        if (j + 1 < nk) {
            const int k0 = (j + 1) * TBK;
            const int nb = b ^ 1;
            #pragma unroll
            for (int q = 0; q < 4; ++q) {
                int row = lrow + q*32;
                cp_async16(smem_u32(As[nb] + row*TSTP + lch*4),
                           A + (size_t)(bm + row)*Ki + k0 + lch*8, 16);
                int brow = bn + row;
                const __half* srcB = Bw + (size_t)(brow < Ni ? brow : 0)*Ki + k0 + lch*8;
                cp_async16(smem_u32(Bs[nb] + row*TSTP + lch*4), srcB, brow < Ni ? 16 : 0);
            }
        }
        CP_COMMIT();
        CP_WAIT1();
        __syncthreads();

        const uint32_t* as = As[b];
        const uint32_t* bs = Bs[b];
        #pragma unroll
        for (int ks = 0; ks < TBK/16; ++ks) {      // 4 k-steps of 16
            uint32_t af[4][4];
            #pragma unroll
            for (int i = 0; i < 4; ++i) {
                const uint32_t* r0 = as + (wm + i*16 + g)*TSTP + ks*8 + t;
                const uint32_t* r1 = r0 + 8*TSTP;
                af[i][0] = r0[0];
                af[i][1] = r1[0];
                af[i][2] = r0[4];
                af[i][3] = r1[4];
            }
            uint32_t bf[4][2];
            #pragma unroll
            for (int jj = 0; jj < 4; ++jj) {
                const uint32_t* base = bs + (wn + jj*8 + g)*TSTP + ks*8 + t;
                bf[jj][0] = base[0];
                bf[jj][1] = base[4];
            }
            #pragma unroll
            for (int i = 0; i < 4; ++i)
                #pragma unroll
                for (int jj = 0; jj < 4; ++jj)
                    mma_f16(acc[i][jj], af[i], bf[jj]);
        }
        __syncthreads();
    }

    // epilogue: c0 (g,2t) c1 (g,2t+1) c2 (g+8,2t) c3 (g+8,2t+1)
    #pragma unroll
    for (int i = 0; i < 4; ++i) {
        int row0 = bm + wm + i*16 + g;
        #pragma unroll
        for (int j = 0; j < 4; ++j) {
            int col = bn + wn + j*8 + 2*t;
            if (col >= Ni) continue;
            size_t o0 = (size_t)row0 * Ni + col;
            size_t o1 = (size_t)(row0 + 8) * Ni + col;
            float2 v0 = make_float2(alpha*acc[i][j][0], alpha*acc[i][j][1]);
            float2 v1 = make_float2(alpha*acc[i][j][2], alpha*acc[i][j][3]);
            if (beta != 0.f) {
                float2 e0 = *(const float2*)(Cin + o0);
                float2 e1 = *(const float2*)(Cin + o1);
                v0.x += beta*e0.x; v0.y += beta*e0.y;
                v1.x += beta*e1.x; v1.y += beta*e1.y;
            }
            *(float2*)(C + o0) = v0;
            *(float2*)(C + o1) = v1;
        }
    }
}

// ---------------- RMS norm: hs16 = f16(rms(x)*w) ----------------
__global__ __launch_bounds__(256) void rms_kernel(
    const float* __restrict__ x, const float* __restrict__ w, __half* __restrict__ out)
{
    int m = blockIdx.x;
    const float* xr = x + (size_t)m * HID;
    float v[8]; float ss = 0.f;
    #pragma unroll
    for (int k = 0; k < 8; ++k) { v[k] = xr[threadIdx.x + k*256]; ss += v[k]*v[k]; }
    ss = blockReduceSum256(ss);
    __shared__ float s_inv;
    if (threadIdx.x == 0) s_inv = rsqrtf(ss * (1.f/HID) + EPS_);
    __syncthreads();
    float inv = s_inv;
    __half* o = out + (size_t)m * HID;
    #pragma unroll
    for (int k = 0; k < 8; ++k) { int c = threadIdx.x + k*256; o[c] = __float2half_rn(v[k]*inv*w[c]); }
}

// ---------------- RoPE in place on qkv ----------------
__global__ void rope_kernel(float* __restrict__ qkv, const int* __restrict__ positions) {
    int idx = blockIdx.x*256 + threadIdx.x;
    const int total = MROWS*(NH+NKV)*32;
    if (idx >= total) return;
    int i = idx & 31; int rest = idx >> 5;
    int head = rest % (NH+NKV); int ml = rest / (NH+NKV);
    int l = ml % L_;
    int col; float mult;
    if (head < NH) { col = head*HD; mult = 1.f; }
    else           { col = NH*HD + (head-NH)*HD; mult = KEY_MULT; }
    float* p = qkv + (size_t)ml*QKV_DIM + col;
    float inv = powf(1e11f, -(float)i/32.0f);
    float ang = (float)positions[l] * inv;
    float c = cosf(ang), s = sinf(ang);
    float x1 = p[i]*mult, x2 = p[i+32]*mult;
    p[i]    = x1*c - x2*s;
    p[i+32] = x2*c + x1*s;
}

// ---------------- Flash attention (causal, GQA 32q/8kv, HD=64) -> fp16 ctx ------
__global__ __launch_bounds__(256) void attn_kernel(
    const float* __restrict__ qkv, __half* __restrict__ ctx)
{
    __shared__ float Qt[64][64];
    __shared__ float KP[64][64];
    __shared__ float Vs[64][64];
    const int tid = threadIdx.x;
    const int ty = tid >> 4, tx = tid & 15;
    const int qb = blockIdx.x, h = blockIdx.y, b = blockIdx.z;
    const int g = h >> 2;
    const int qcol = h*HD;
    const int kcol = NH*HD + g*HD;
    const int vcol = NH*HD + NKV*HD + g*HD;

    for (int i = tid; i < 64*16; i += 256) {
        int r = i >> 4, d4 = (i & 15) << 2;
        float4 v = *(const float4*)(qkv + (size_t)(b*L_ + qb*64 + r)*QKV_DIM + qcol + d4);
        Qt[d4+0][r]=v.x; Qt[d4+1][r]=v.y; Qt[d4+2][r]=v.z; Qt[d4+3][r]=v.w;
    }

    float acc[4][4]; float m_i[4], l_i[4];
    #pragma unroll
    for (int i = 0; i < 4; ++i) {
        m_i[i] = -1e30f; l_i[i] = 0.f;
        #pragma unroll
        for (int j = 0; j < 4; ++j) acc[i][j] = 0.f;
    }

    for (int j = 0; j <= qb; ++j) {
        __syncthreads();
        for (int i = tid; i < 64*16; i += 256) {
            int r = i >> 4, d4 = (i & 15) << 2;
            const float* rowp = qkv + (size_t)(b*L_ + j*64 + r)*QKV_DIM;
            float4 kv = *(const float4*)(rowp + kcol + d4);
            KP[d4+0][r]=kv.x; KP[d4+1][r]=kv.y; KP[d4+2][r]=kv.z; KP[d4+3][r]=kv.w;
            *(float4*)(&Vs[r][d4]) = *(const float4*)(rowp + vcol + d4);
        }
        __syncthreads();

        float s[4][4];
        #pragma unroll
        for (int i = 0; i < 4; ++i)
            #pragma unroll
            for (int jj = 0; jj < 4; ++jj) s[i][jj] = 0.f;
        #pragma unroll 8
        for (int kk = 0; kk < 64; ++kk) {
            float a[4], bb[4];
            #pragma unroll
            for (int i = 0; i < 4; ++i)  a[i]  = Qt[kk][ty*4+i];
            #pragma unroll
            for (int jj = 0; jj < 4; ++jj) bb[jj] = KP[kk][tx*4+jj];
            #pragma unroll
            for (int i = 0; i < 4; ++i)
                #pragma unroll
                for (int jj = 0; jj < 4; ++jj) s[i][jj] = fmaf(a[i], bb[jj], s[i][jj]);
        }
        const bool diag = (j == qb);
        #pragma unroll
        for (int i = 0; i < 4; ++i)
            #pragma unroll
            for (int jj = 0; jj < 4; ++jj) {
                bool masked = diag && ((tx*4+jj) > (ty*4+i));
                s[i][jj] = masked ? -1e30f : s[i][jj]*0.125f;
            }

        float p[4][4];
        #pragma unroll
        for (int i = 0; i < 4; ++i) {
            float rm = fmaxf(fmaxf(s[i][0], s[i][1]), fmaxf(s[i][2], s[i][3]));
            #pragma unroll
            for (int o = 8; o; o >>= 1) rm = fmaxf(rm, __shfl_xor_sync(0xffffffffu, rm, o));
            float mnew = fmaxf(m_i[i], rm);
            float rs = 0.f;
            #pragma unroll
            for (int jj = 0; jj < 4; ++jj) { p[i][jj] = __expf(s[i][jj] - mnew); rs += p[i][jj]; }
            #pragma unroll
            for (int o = 8; o; o >>= 1) rs += __shfl_xor_sync(0xffffffffu, rs, o);
            float corr = __expf(m_i[i] - mnew);
            l_i[i] = l_i[i]*corr + rs;
            m_i[i] = mnew;
            #pragma unroll
            for (int jj = 0; jj < 4; ++jj) acc[i][jj] *= corr;
        }

        __syncthreads();
        #pragma unroll
        for (int i = 0; i < 4; ++i)
            #pragma unroll
            for (int jj = 0; jj < 4; ++jj) KP[tx*4+jj][ty*4+i] = p[i][jj];
        __syncthreads();

        #pragma unroll 8
        for (int kk = 0; kk < 64; ++kk) {
            float a[4], bb[4];
            #pragma unroll
            for (int i = 0; i < 4; ++i)  a[i]  = KP[kk][ty*4+i];
            #pragma unroll
            for (int jj = 0; jj < 4; ++jj) bb[jj] = Vs[kk][tx*4+jj];
            #pragma unroll
            for (int i = 0; i < 4; ++i)
                #pragma unroll
                for (int jj = 0; jj < 4; ++jj) acc[i][jj] = fmaf(a[i], bb[jj], acc[i][jj]);
        }
    }

    #pragma unroll
    for (int i = 0; i < 4; ++i) {
        float invl = 1.f / l_i[i];
        #pragma unroll
        for (int jj = 0; jj < 4; ++jj)
            ctx[(size_t)(b*L_ + qb*64 + ty*4+i)*HID + h*HD + tx*4 + jj] =
                __float2half_rn(acc[i][jj]*invl);
    }
}

// ---------------- depthwise causal conv (MK=4) + mup + bias + SiLU ----------------
__global__ void conv_kernel(const float* __restrict__ proj, const float* __restrict__ cw,
                            const float* __restrict__ cb, float* __restrict__ out)
{
    int idx = blockIdx.x*256 + threadIdx.x;
    if (idx >= MROWS*CONV_DIM) return;
    int c = idx % CONV_DIM;
    int ml = idx / CONV_DIM;
    int l = ml % L_, b = ml / L_;
    float mupf = (c < DSSM) ? 0.9f : ((c < DSSM+MS) ? 0.8f : 1.1f);
    float s = 0.f;
    #pragma unroll
    for (int k = 0; k < MK; ++k) {
        int ls = l + k - (MK-1);
        if (ls >= 0) s += proj[(size_t)(b*L_+ls)*PROJ_DIM + DSSM + c] * cw[c*MK + k];
    }
    s = mupf*s + cb[c];
    out[idx] = siluf(s);
}

// ---------------- Mamba2 selective scan ----------------
#define SCT 32
__global__ __launch_bounds__(256) void scan_kernel(
    const float* __restrict__ conv, const float* __restrict__ proj,
    const float* __restrict__ A_log, const float* __restrict__ dt_bias,
    const float* __restrict__ Dp, float* __restrict__ y)
{
    const int b = blockIdx.x / MH, h = blockIdx.x % MH;
    const int tid = threadIdx.x;
    const int p = tid >> 2, sg = tid & 3, s0 = sg*16;
    const float Ah = -__expf(A_log[h]);
    const float Dh = Dp[h];
    const float dtb = dt_bias[h];
    float st[16];
    #pragma unroll
    for (int i = 0; i < 16; ++i) st[i] = 0.f;

    __shared__ float xs[SCT][64], Bsh[SCT][64], Csh[SCT][64], dts[SCT];

    for (int l0 = 0; l0 < L_; l0 += SCT) {
        __syncthreads();
        for (int i = tid; i < SCT*64; i += 256) {
            int t = i >> 6, c = i & 63;
            size_t base = (size_t)(b*L_ + l0 + t)*CONV_DIM;
            xs[t][c]  = conv[base + h*64 + c];
            Bsh[t][c] = conv[base + DSSM + c];
            Csh[t][c] = conv[base + DSSM + MS + c];
        }
        for (int i = tid; i < SCT; i += 256) {
            float r = proj[(size_t)(b*L_ + l0 + i)*PROJ_DIM + (PROJ_DIM-MH) + h] * 1.2f + dtb;
            dts[i] = (r > 20.f) ? r : log1pf(expf(r));   // softplus
        }
        __syncthreads();
        for (int t = 0; t < SCT; ++t) {
            float dt = dts[t];
            float dA = __expf(dt * Ah);
            float xv = xs[t][p];
            float coef = dt * xv;
            float acc = 0.f;
            #pragma unroll
            for (int ss = 0; ss < 16; ++ss) {
                st[ss] = st[ss]*dA + coef*Bsh[t][s0+ss];
                acc = fmaf(st[ss], Csh[t][s0+ss], acc);
            }
            acc += __shfl_xor_sync(0xffffffffu, acc, 1);
            acc += __shfl_xor_sync(0xffffffffu, acc, 2);
            if (sg == 0)
                y[(size_t)(b*L_ + l0 + t)*DSSM + h*64 + p] = acc + xv*Dh;
        }
    }
}

// ---------------- gating + RMS -> fp16 ----------------
__global__ __launch_bounds__(256) void gate_rms_kernel(
    const float* __restrict__ y, const float* __restrict__ proj,
    const float* __restrict__ w, __half* __restrict__ out)
{
    int m = blockIdx.x;
    const float* yr = y + (size_t)m*DSSM;
    const float* zr = proj + (size_t)m*PROJ_DIM;
    float v[8]; float ss = 0.f;
    #pragma unroll
    for (int k = 0; k < 8; ++k) {
        int c = threadIdx.x + k*256;
        float z = zr[c];
        float gv = yr[c] * siluf(z);
        v[k] = gv; ss += gv*gv;
    }
    ss = blockReduceSum256(ss);
    __shared__ float s_inv;
    if (threadIdx.x == 0) s_inv = rsqrtf(ss * (1.f/DSSM) + EPS_);
    __syncthreads();
    float inv = s_inv;
    __half* o = out + (size_t)m*DSSM;
    #pragma unroll
    for (int k = 0; k < 8; ++k) { int c = threadIdx.x + k*256; o[c] = __float2half_rn(v[k]*inv*w[c]); }
}

// ---------------- combine: h = as + residual ; hn16 = f16(rms(h)*w) ----------------
__global__ __launch_bounds__(256) void combine_kernel(
    const float* __restrict__ as_, const float* __restrict__ resid,
    const float* __restrict__ w, float* __restrict__ h, __half* __restrict__ hn)
{
    int m = blockIdx.x;
    const float* ar = as_  + (size_t)m*HID;
    const float* rr = resid + (size_t)m*HID;
    float v[8]; float ss = 0.f;
    #pragma unroll
    for (int k = 0; k < 8; ++k) {
        int c = threadIdx.x + k*256;
        float hv = ar[c] + rr[c];
        v[k] = hv; ss += hv*hv;
    }
    ss = blockReduceSum256(ss);
    __shared__ float s_inv;
    if (threadIdx.x == 0) s_inv = rsqrtf(ss * (1.f/HID) + EPS_);
    __syncthreads();
    float inv = s_inv;
    float* ho = h + (size_t)m*HID;
    __half* no = hn + (size_t)m*HID;
    #pragma unroll
    for (int k = 0; k < 8; ++k) {
        int c = threadIdx.x + k*256;
        ho[c] = v[k];
        no[c] = __float2half_rn(v[k]*inv*w[c]);
    }
}

// ---------------- SwiGLU activation -> fp16 ----------------
__global__ void act_kernel(const float* __restrict__ gu, __half* __restrict__ act) {
    int idx = blockIdx.x*256 + threadIdx.x;
    if (idx >= MROWS*INTER) return;
    int m = idx / INTER, i = idx % INTER;
    const float* row = gu + (size_t)m*(2*INTER);
    float gate = row[i] * GATE_MULT;
    float up   = row[INTER + i];
    act[idx] = __float2half_rn(siluf(gate) * up);
}

// ---------------- host launcher ----------------
extern "C" void kernel_launch(void* const* d_in, const int* in_sizes, int n_in,
                              void* d_out, int out_size)
{
    const float* hidden      = (const float*)d_in[0];
    const int*   positions   = (const int*)  d_in[1];
    const float* w_in_ln     = (const float*)d_in[2];
    const float* qkv_w       = (const float*)d_in[3];
    const float* o_w         = (const float*)d_in[4];
    const float* in_proj_w   = (const float*)d_in[5];
    const float* conv_w      = (const float*)d_in[6];
    const float* conv_b      = (const float*)d_in[7];
    const float* A_log       = (const float*)d_in[8];
    const float* dt_bias     = (const float*)d_in[9];
    const float* Dp          = (const float*)d_in[10];
    const float* ssm_norm_w  = (const float*)d_in[11];
    const float* out_proj_w  = (const float*)d_in[12];
    const float* w_pre_ff_ln = (const float*)d_in[13];
    const float* gate_up_w   = (const float*)d_in[14];
    const float* down_w      = (const float*)d_in[15];
    float* out = (float*)d_out;

    float *qkv, *proj, *conv, *y, *as_, *h, *gu;
    __half *hs16, *ctx16, *gt16, *hn16, *act16, *w16;
    cudaGetSymbolAddress((void**)&qkv,  g_qkv);
    cudaGetSymbolAddress((void**)&proj, g_proj);
    cudaGetSymbolAddress((void**)&conv, g_conv);
    cudaGetSymbolAddress((void**)&y,    g_y);
    cudaGetSymbolAddress((void**)&as_,  g_as);
    cudaGetSymbolAddress((void**)&h,    g_h);
    cudaGetSymbolAddress((void**)&gu,   g_gu);
    cudaGetSymbolAddress((void**)&hs16, g_hs16);
    cudaGetSymbolAddress((void**)&ctx16,g_ctx16);
    cudaGetSymbolAddress((void**)&gt16, g_gt16);
    cudaGetSymbolAddress((void**)&hn16, g_hn16);
    cudaGetSymbolAddress((void**)&act16,g_act16);
    cudaGetSymbolAddress((void**)&w16,  g_w16);

    cudaFuncSetAttribute(gemm_f16, cudaFuncAttributeMaxDynamicSharedMemorySize, GSMEM_BYTES);

    const int MT = MROWS/TBM;   // 16

    // 0. weight conversion fp32 -> fp16
    #define CVT(src, dstoff, n) \
        cvt_f16_kernel<<<((n)/4 + 255)/256, 256>>>(src, w16 + (size_t)(dstoff), (n)/4)
    CVT(qkv_w,      W16_QKV,     QKV_DIM*HID);
    CVT(in_proj_w,  W16_INPROJ,  PROJ_DIM*HID);
    CVT(o_w,        W16_O,       HID*HID);
    CVT(out_proj_w, W16_OUTPROJ, HID*DSSM);
    CVT(gate_up_w,  W16_GATEUP,  2*INTER*HID);
    CVT(down_w,     W16_DOWN,    HID*INTER);
    #undef CVT

    // 1. input RMS norm (fp16 out)
    rms_kernel<<<MROWS, 256>>>(hidden, w_in_ln, hs16);

    // 2. qkv = (hs*ATTN_IN) @ qkv_w^T ; proj = (hs*SSM_IN) @ in_proj_w^T
    gemm_f16<<<dim3(QKV_DIM/TBN, MT), 256, GSMEM_BYTES>>>(QKV_DIM, HID, ATTN_IN,
                                            hs16, w16 + W16_QKV, 0.f, nullptr, qkv);
    gemm_f16<<<dim3((PROJ_DIM+TBN-1)/TBN, MT), 256, GSMEM_BYTES>>>(PROJ_DIM, HID, SSM_IN,
                                            hs16, w16 + W16_INPROJ, 0.f, nullptr, proj);

    // 3. RoPE
    rope_kernel<<<(MROWS*(NH+NKV)*32 + 255)/256, 256>>>(qkv, positions);

    // 4. attention (fp16 ctx out)
    attn_kernel<<<dim3(L_/64, NH, B_), 256>>>(qkv, ctx16);

    // 5. as = ATTN_OUT * ctx @ o_w^T
    gemm_f16<<<dim3(HID/TBN, MT), 256, GSMEM_BYTES>>>(HID, HID, ATTN_OUT,
                                            ctx16, w16 + W16_O, 0.f, nullptr, as_);

    // 6. mamba
    conv_kernel<<<(MROWS*CONV_DIM + 255)/256, 256>>>(proj, conv_w, conv_b, conv);
    scan_kernel<<<B_*MH, 256>>>(conv, proj, A_log, dt_bias, Dp, y);
    gate_rms_kernel<<<MROWS, 256>>>(y, proj, ssm_norm_w, gt16);
    gemm_f16<<<dim3(HID/TBN, MT), 256, GSMEM_BYTES>>>(HID, DSSM, SSM_OUT,
                                            gt16, w16 + W16_OUTPROJ, 1.f, as_, as_);

    // 7. combine + pre-FF RMS (fp16 hn out)
    combine_kernel<<<MROWS, 256>>>(as_, hidden, w_pre_ff_ln, h, hn16);

    // 8. MLP
    gemm_f16<<<dim3(2*INTER/TBN, MT), 256, GSMEM_BYTES>>>(2*INTER, HID, 1.f,
                                            hn16, w16 + W16_GATEUP, 0.f, nullptr, gu);
    act_kernel<<<(MROWS*INTER + 255)/256, 256>>>(gu, act16);
    gemm_f16<<<dim3(HID/TBN, MT), 256, GSMEM_BYTES>>>(HID, INTER, DOWN_MULT,
                                            act16, w16 + W16_DOWN, 1.f, h, out);
    (void)in_sizes; (void)n_in; (void)out_size;
}

// round 7
// speedup vs baseline: 5.0504x; 1.2143x over previous
#include <cuda_runtime.h>
#include <cuda_fp16.h>
#include <math.h>
#include <stdint.h>

#define B_ 2
#define L_ 1024
#define HID 2048
#define NH 32
#define HD 64
#define NKV 8
#define INTER 8192
#define DSSM 2048
#define MH 32
#define MP 64
#define MS 64
#define MK 4
#define CONV_DIM (DSSM + 2*MS)          // 2176
#define PROJ_DIM (2*DSSM + 2*MS + MH)   // 4256
#define QKV_DIM (NH*HD + 2*NKV*HD)      // 3072
#define MROWS (B_*L_)                   // 2048

#define ATTN_IN 1.2f
#define ATTN_OUT 0.8f
#define KEY_MULT 0.7f
#define SSM_IN 1.1f
#define SSM_OUT 0.9f
#define GATE_MULT 0.9f
#define DOWN_MULT 0.8f
#define EPS_ 1e-5f

// ---------------- scratch (device globals; no allocation allowed) ----------------
__device__ float  g_qkv [MROWS*QKV_DIM];
__device__ float  g_proj[MROWS*PROJ_DIM];
__device__ float  g_conv[MROWS*CONV_DIM];
__device__ float  g_y   [MROWS*DSSM];
__device__ float  g_as  [MROWS*HID];
__device__ float  g_h   [MROWS*HID];
__device__ float  g_gu  [(size_t)MROWS*2*INTER];

__device__ __half g_hs16 [MROWS*HID];
__device__ __half g_ctx16[MROWS*HID];
__device__ __half g_gt16 [MROWS*DSSM];
__device__ __half g_hn16 [MROWS*HID];
__device__ __half g_act16[(size_t)MROWS*INTER];
__device__ __half g_q16  [MROWS*NH*HD];
__device__ __half g_k16  [B_*NKV*L_*HD];
__device__ __half g_v16t [B_*NKV*HD*L_];

// fp16 weights, one big buffer
#define W16_QKV     0
#define W16_INPROJ  (W16_QKV    + QKV_DIM*HID)
#define W16_O       (W16_INPROJ + PROJ_DIM*HID)
#define W16_OUTPROJ (W16_O      + HID*HID)
#define W16_GATEUP  (W16_OUTPROJ+ HID*DSSM)
#define W16_DOWN    (W16_GATEUP + 2*INTER*HID)
#define W16_TOTAL   (W16_DOWN   + HID*INTER)
__device__ __half g_w16[W16_TOTAL];

// ---------------- helpers ----------------
__device__ __forceinline__ float blockReduceSum256(float v) {
    __shared__ float sh[8];
    int lane = threadIdx.x & 31, w = threadIdx.x >> 5;
    #pragma unroll
    for (int o = 16; o; o >>= 1) v += __shfl_xor_sync(0xffffffffu, v, o);
    if (lane == 0) sh[w] = v;
    __syncthreads();
    v = (threadIdx.x < 8) ? sh[threadIdx.x] : 0.f;
    if (w == 0) {
        #pragma unroll
        for (int o = 4; o; o >>= 1) v += __shfl_xor_sync(0xffu, v, o);
    }
    return v;
}

__device__ __forceinline__ float siluf(float x) { return x / (1.f + __expf(-x)); }

__device__ __forceinline__ void mma_f16(float* c, const uint32_t* a, const uint32_t* b) {
    asm volatile(
        "mma.sync.aligned.m16n8k16.row.col.f32.f16.f16.f32 "
        "{%0,%1,%2,%3}, {%4,%5,%6,%7}, {%8,%9}, {%0,%1,%2,%3};"
        : "+f"(c[0]), "+f"(c[1]), "+f"(c[2]), "+f"(c[3])
        : "r"(a[0]), "r"(a[1]), "r"(a[2]), "r"(a[3]), "r"(b[0]), "r"(b[1]));
}

__device__ __forceinline__ uint32_t smem_u32(const void* p) {
    uint32_t a;
    asm("{ .reg .u64 t; cvta.to.shared.u64 t, %1; cvt.u32.u64 %0, t; }" : "=r"(a) : "l"(p));
    return a;
}
__device__ __forceinline__ void cp_async16(uint32_t dst, const void* src, int srcBytes) {
    asm volatile("cp.async.cg.shared.global [%0], [%1], 16, %2;"
                 :: "r"(dst), "l"(src), "r"(srcBytes));
}
#define CP_COMMIT() asm volatile("cp.async.commit_group;" ::: "memory")
#define CP_WAIT1()  asm volatile("cp.async.wait_group 1;"  ::: "memory")

__device__ __forceinline__ uint32_t packh2(float a, float b) {
    __half2 h = __floats2half2_rn(a, b);
    return *(uint32_t*)&h;
}

// ---------------- fp32 -> fp16 weight convert ----------------
__global__ void cvt_f16_kernel(const float* __restrict__ in, __half* __restrict__ out, int n4) {
    int i = blockIdx.x*256 + threadIdx.x;
    if (i >= n4) return;
    float4 v = *(const float4*)(in + (size_t)i*4);
    __half2 a = __floats2half2_rn(v.x, v.y);
    __half2 b = __floats2half2_rn(v.z, v.w);
    *(uint2*)(out + (size_t)i*4) = make_uint2(*(uint32_t*)&a, *(uint32_t*)&b);
}

// ---------------- FP16 tensor-core GEMM ----------------
#define TBM 128
#define TBN 128
#define TBK 64
#define TSTP 36
#define STGP (128*TSTP)
#define GSMEM_BYTES (4*STGP*4)           // 73728 B

__global__ __launch_bounds__(256, 2) void gemm_f16(
    int Ni, int Ki, float alpha,
    const __half* __restrict__ A, const __half* __restrict__ Bw,
    float beta, const float* __restrict__ Cin, float* __restrict__ C)
{
    extern __shared__ uint32_t smp[];
    uint32_t* As[2] = { smp,          smp + 2*STGP };
    uint32_t* Bs[2] = { smp + STGP,   smp + 3*STGP };

    const int tid = threadIdx.x;
    const int bm = blockIdx.y * TBM, bn = blockIdx.x * TBN;
    const int warp = tid >> 5, lane = tid & 31;
    const int g = lane >> 2, t = lane & 3;
    const int wm = (warp >> 2) * 64;
    const int wn = (warp & 3) * 32;

    const int lrow = tid >> 3;
    const int lch  = tid & 7;

    const int nk = Ki / TBK;

    {
        #pragma unroll
        for (int q = 0; q < 4; ++q) {
            int row = lrow + q*32;
            cp_async16(smem_u32(As[0] + row*TSTP + lch*4),
                       A + (size_t)(bm + row)*Ki + lch*8, 16);
            int brow = bn + row;
            const __half* srcB = Bw + (size_t)(brow < Ni ? brow : 0)*Ki + lch*8;
            cp_async16(smem_u32(Bs[0] + row*TSTP + lch*4), srcB, brow < Ni ? 16 : 0);
        }
        CP_COMMIT();
    }

    float acc[4][4][4];
    #pragma unroll
    for (int i = 0; i < 4; ++i)
        #pragma unroll
        for (int j = 0; j < 4; ++j)
            #pragma unroll
            for (int r = 0; r < 4; ++r) acc[i][j][r] = 0.f;

    for (int j = 0; j < nk; ++j) {
        const int b = j & 1;
        if (j + 1 < nk) {
            const int k0 = (j + 1) * TBK;
            const int nb = b ^ 1;
            #pragma unroll
            for (int q = 0; q < 4; ++q) {
                int row = lrow + q*32;
                cp_async16(smem_u32(As[nb] + row*TSTP + lch*4),
                           A + (size_t)(bm + row)*Ki + k0 + lch*8, 16);
                int brow = bn + row;
                const __half* srcB = Bw + (size_t)(brow < Ni ? brow : 0)*Ki + k0 + lch*8;
                cp_async16(smem_u32(Bs[nb] + row*TSTP + lch*4), srcB, brow < Ni ? 16 : 0);
            }
        }
        CP_COMMIT();
        CP_WAIT1();
        __syncthreads();

        const uint32_t* as = As[b];
        const uint32_t* bs = Bs[b];
        #pragma unroll
        for (int ks = 0; ks < TBK/16; ++ks) {
            uint32_t af[4][4];
            #pragma unroll
            for (int i = 0; i < 4; ++i) {
                const uint32_t* r0 = as + (wm + i*16 + g)*TSTP + ks*8 + t;
                const uint32_t* r1 = r0 + 8*TSTP;
                af[i][0] = r0[0];
                af[i][1] = r1[0];
                af[i][2] = r0[4];
                af[i][3] = r1[4];
            }
            uint32_t bf[4][2];
            #pragma unroll
            for (int jj = 0; jj < 4; ++jj) {
                const uint32_t* base = bs + (wn + jj*8 + g)*TSTP + ks*8 + t;
                bf[jj][0] = base[0];
                bf[jj][1] = base[4];
            }
            #pragma unroll
            for (int i = 0; i < 4; ++i)
                #pragma unroll
                for (int jj = 0; jj < 4; ++jj)
                    mma_f16(acc[i][jj], af[i], bf[jj]);
        }
        __syncthreads();
    }

    #pragma unroll
    for (int i = 0; i < 4; ++i) {
        int row0 = bm + wm + i*16 + g;
        #pragma unroll
        for (int j = 0; j < 4; ++j) {
            int col = bn + wn + j*8 + 2*t;
            if (col >= Ni) continue;
            size_t o0 = (size_t)row0 * Ni + col;
            size_t o1 = (size_t)(row0 + 8) * Ni + col;
            float2 v0 = make_float2(alpha*acc[i][j][0], alpha*acc[i][j][1]);
            float2 v1 = make_float2(alpha*acc[i][j][2], alpha*acc[i][j][3]);
            if (beta != 0.f) {
                float2 e0 = *(const float2*)(Cin + o0);
                float2 e1 = *(const float2*)(Cin + o1);
                v0.x += beta*e0.x; v0.y += beta*e0.y;
                v1.x += beta*e1.x; v1.y += beta*e1.y;
            }
            *(float2*)(C + o0) = v0;
            *(float2*)(C + o1) = v1;
        }
    }
}

// ---------------- RMS norm: hs16 = f16(rms(x)*w) ----------------
__global__ __launch_bounds__(256) void rms_kernel(
    const float* __restrict__ x, const float* __restrict__ w, __half* __restrict__ out)
{
    int m = blockIdx.x;
    const float* xr = x + (size_t)m * HID;
    float v[8]; float ss = 0.f;
    #pragma unroll
    for (int k = 0; k < 8; ++k) { v[k] = xr[threadIdx.x + k*256]; ss += v[k]*v[k]; }
    ss = blockReduceSum256(ss);
    __shared__ float s_inv;
    if (threadIdx.x == 0) s_inv = rsqrtf(ss * (1.f/HID) + EPS_);
    __syncthreads();
    float inv = s_inv;
    __half* o = out + (size_t)m * HID;
    #pragma unroll
    for (int k = 0; k < 8; ++k) { int c = threadIdx.x + k*256; o[c] = __float2half_rn(v[k]*inv*w[c]); }
}

// ---------------- RoPE -> fp16 q (scaled by 1/8) and k (head-major) --------------
__global__ void rope_kernel(const float* __restrict__ qkv, const int* __restrict__ positions,
                            __half* __restrict__ q16, __half* __restrict__ k16) {
    int idx = blockIdx.x*256 + threadIdx.x;
    const int total = MROWS*(NH+NKV)*32;
    if (idx >= total) return;
    int i = idx & 31; int rest = idx >> 5;
    int head = rest % (NH+NKV); int ml = rest / (NH+NKV);
    int l = ml % L_, b = ml / L_;
    float inv = powf(1e11f, -(float)i/32.0f);
    float ang = (float)positions[l] * inv;
    float c = cosf(ang), s = sinf(ang);
    if (head < NH) {
        const float* p = qkv + (size_t)ml*QKV_DIM + head*HD;
        float x1 = p[i], x2 = p[i+32];
        __half* o = q16 + (size_t)ml*(NH*HD) + head*HD;
        o[i]    = __float2half_rn((x1*c - x2*s) * 0.125f);
        o[i+32] = __float2half_rn((x2*c + x1*s) * 0.125f);
    } else {
        int g = head - NH;
        const float* p = qkv + (size_t)ml*QKV_DIM + NH*HD + g*HD;
        float x1 = p[i]*KEY_MULT, x2 = p[i+32]*KEY_MULT;
        __half* o = k16 + ((size_t)(b*NKV + g)*L_ + l)*HD;
        o[i]    = __float2half_rn(x1*c - x2*s);
        o[i+32] = __float2half_rn(x2*c + x1*s);
    }
}

// ---------------- V transpose: fp32 qkv v-part -> v16t [b][g][d][L] --------------
__global__ __launch_bounds__(256) void vtrans_kernel(
    const float* __restrict__ qkv, __half* __restrict__ v16t)
{
    __shared__ __half ts[64][65];
    const int lt = blockIdx.x, g = blockIdx.y, b = blockIdx.z;
    const int vcol = NH*HD + NKV*HD + g*HD;
    const int tid = threadIdx.x;
    #pragma unroll
    for (int q = 0; q < 16; ++q) {
        int idx = tid + q*256;
        int row = idx >> 6, col = idx & 63;
        float v = qkv[(size_t)(b*L_ + lt*64 + row)*QKV_DIM + vcol + col];
        ts[col][row] = __float2half_rn(v);
    }
    __syncthreads();
    #pragma unroll
    for (int q = 0; q < 16; ++q) {
        int idx = tid + q*256;
        int d = idx >> 6, l = idx & 63;
        v16t[((size_t)(b*NKV + g)*HD + d)*L_ + lt*64 + l] = ts[d][l];
    }
}

// ---------------- tensor-core flash attention (causal, GQA, HD=64) --------------
// 4 warps, warp = 16 q-rows. fp16 mma for QK^T and PV, fp32 online softmax.
__global__ __launch_bounds__(128) void attn_kernel(
    const __half* __restrict__ q16, const __half* __restrict__ k16,
    const __half* __restrict__ v16t, __half* __restrict__ ctx)
{
    __shared__ uint32_t Qs[64*36];
    __shared__ uint32_t Ks[64*36];
    __shared__ uint32_t Vs[64*36];
    const int tid = threadIdx.x;
    const int warp = tid >> 5, lane = tid & 31;
    const int g = lane >> 2, t = lane & 3;
    const int wm = warp*16;
    const int qb = blockIdx.x, h = blockIdx.y, b = blockIdx.z;
    const int kg = h >> 2;

    {   // load Q tile
        const __half* qp = q16 + (size_t)(b*L_ + qb*64)*(NH*HD) + h*HD;
        #pragma unroll
        for (int q = 0; q < 4; ++q) {
            int idx = tid + q*128;
            int row = idx >> 3, ch = idx & 7;
            *(uint4*)(&Qs[row*36 + ch*4]) =
                *(const uint4*)(qp + (size_t)row*(NH*HD) + ch*8);
        }
    }
    __syncthreads();

    uint32_t aq[4][4];
    #pragma unroll
    for (int ks = 0; ks < 4; ++ks) {
        const uint32_t* r0 = Qs + (wm + g)*36 + ks*8 + t;
        const uint32_t* r1 = Qs + (wm + g + 8)*36 + ks*8 + t;
        aq[ks][0] = r0[0]; aq[ks][1] = r1[0]; aq[ks][2] = r0[4]; aq[ks][3] = r1[4];
    }

    float oacc[8][4];
    #pragma unroll
    for (int jj = 0; jj < 8; ++jj)
        #pragma unroll
        for (int r = 0; r < 4; ++r) oacc[jj][r] = 0.f;
    float m_a = -1e30f, m_b = -1e30f, l_a = 0.f, l_b = 0.f;

    const __half* kp = k16 + (size_t)(b*NKV + kg)*L_*HD;
    const __half* vp = v16t + (size_t)(b*NKV + kg)*HD*L_;

    for (int j = 0; j <= qb; ++j) {
        __syncthreads();
        #pragma unroll
        for (int q = 0; q < 4; ++q) {
            int idx = tid + q*128;
            int row = idx >> 3, ch = idx & 7;
            *(uint4*)(&Ks[row*36 + ch*4]) =
                *(const uint4*)(kp + (size_t)(j*64 + row)*HD + ch*8);
            *(uint4*)(&Vs[row*36 + ch*4]) =
                *(const uint4*)(vp + (size_t)row*L_ + j*64 + ch*8);
        }
        __syncthreads();

        // S = Q @ K^T
        float sacc[8][4];
        #pragma unroll
        for (int jj = 0; jj < 8; ++jj)
            #pragma unroll
            for (int r = 0; r < 4; ++r) sacc[jj][r] = 0.f;
        #pragma unroll
        for (int ks = 0; ks < 4; ++ks) {
            #pragma unroll
            for (int jj = 0; jj < 8; ++jj) {
                uint32_t bk[2];
                const uint32_t* base = Ks + (jj*8 + g)*36 + ks*8 + t;
                bk[0] = base[0]; bk[1] = base[4];
                mma_f16(sacc[jj], aq[ks], bk);
            }
        }

        // causal mask on diagonal tile
        if (j == qb) {
            const int ra = wm + g, rb = ra + 8;
            #pragma unroll
            for (int jj = 0; jj < 8; ++jj) {
                int c0 = jj*8 + 2*t, c1 = c0 + 1;
                if (c0 > ra) sacc[jj][0] = -1e30f;
                if (c1 > ra) sacc[jj][1] = -1e30f;
                if (c0 > rb) sacc[jj][2] = -1e30f;
                if (c1 > rb) sacc[jj][3] = -1e30f;
            }
        }

        // online softmax
        float mx_a = -1e30f, mx_b = -1e30f;
        #pragma unroll
        for (int jj = 0; jj < 8; ++jj) {
            mx_a = fmaxf(mx_a, fmaxf(sacc[jj][0], sacc[jj][1]));
            mx_b = fmaxf(mx_b, fmaxf(sacc[jj][2], sacc[jj][3]));
        }
        mx_a = fmaxf(mx_a, __shfl_xor_sync(0xffffffffu, mx_a, 1));
        mx_a = fmaxf(mx_a, __shfl_xor_sync(0xffffffffu, mx_a, 2));
        mx_b = fmaxf(mx_b, __shfl_xor_sync(0xffffffffu, mx_b, 1));
        mx_b = fmaxf(mx_b, __shfl_xor_sync(0xffffffffu, mx_b, 2));
        float mna = fmaxf(m_a, mx_a), mnb = fmaxf(m_b, mx_b);
        float ca = __expf(m_a - mna), cb = __expf(m_b - mnb);
        m_a = mna; m_b = mnb;
        float sa = 0.f, sb = 0.f;
        #pragma unroll
        for (int jj = 0; jj < 8; ++jj) {
            sacc[jj][0] = __expf(sacc[jj][0] - mna);
            sacc[jj][1] = __expf(sacc[jj][1] - mna);
            sacc[jj][2] = __expf(sacc[jj][2] - mnb);
            sacc[jj][3] = __expf(sacc[jj][3] - mnb);
            sa += sacc[jj][0] + sacc[jj][1];
            sb += sacc[jj][2] + sacc[jj][3];
        }
        sa += __shfl_xor_sync(0xffffffffu, sa, 1);
        sa += __shfl_xor_sync(0xffffffffu, sa, 2);
        sb += __shfl_xor_sync(0xffffffffu, sb, 1);
        sb += __shfl_xor_sync(0xffffffffu, sb, 2);
        l_a = l_a*ca + sa; l_b = l_b*cb + sb;
        #pragma unroll
        for (int jj = 0; jj < 8; ++jj) {
            oacc[jj][0] *= ca; oacc[jj][1] *= ca;
            oacc[jj][2] *= cb; oacc[jj][3] *= cb;
        }

        // P fp16 fragments (accumulator layout == A-operand layout)
        uint32_t aP[4][4];
        #pragma unroll
        for (int s = 0; s < 4; ++s) {
            aP[s][0] = packh2(sacc[2*s][0],   sacc[2*s][1]);
            aP[s][1] = packh2(sacc[2*s][2],   sacc[2*s][3]);
            aP[s][2] = packh2(sacc[2*s+1][0], sacc[2*s+1][1]);
            aP[s][3] = packh2(sacc[2*s+1][2], sacc[2*s+1][3]);
        }

        // O += P @ V
        #pragma unroll
        for (int s = 0; s < 4; ++s) {
            #pragma unroll
            for (int jj = 0; jj < 8; ++jj) {
                uint32_t bv[2];
                const uint32_t* base = Vs + (jj*8 + g)*36 + s*8 + t;
                bv[0] = base[0]; bv[1] = base[4];
                mma_f16(oacc[jj], aP[s], bv);
            }
        }
    }

    // epilogue
    float ila = 1.f / l_a, ilb = 1.f / l_b;
    int ra = qb*64 + wm + g;
    __half* op = ctx + (size_t)(b*L_ + ra)*HID + h*HD + 2*t;
    #pragma unroll
    for (int jj = 0; jj < 8; ++jj) {
        *(uint32_t*)(op + jj*8) = packh2(oacc[jj][0]*ila, oacc[jj][1]*ila);
        *(uint32_t*)(op + 8*HID + jj*8) = packh2(oacc[jj][2]*ilb, oacc[jj][3]*ilb);
    }
}

// ---------------- depthwise causal conv (MK=4) + mup + bias + SiLU ----------------
__global__ void conv_kernel(const float* __restrict__ proj, const float* __restrict__ cw,
                            const float* __restrict__ cb, float* __restrict__ out)
{
    int idx = blockIdx.x*256 + threadIdx.x;
    if (idx >= MROWS*CONV_DIM) return;
    int c = idx % CONV_DIM;
    int ml = idx / CONV_DIM;
    int l = ml % L_, b = ml / L_;
    float mupf = (c < DSSM) ? 0.9f : ((c < DSSM+MS) ? 0.8f : 1.1f);
    float s = 0.f;
    #pragma unroll
    for (int k = 0; k < MK; ++k) {
        int ls = l + k - (MK-1);
        if (ls >= 0) s += proj[(size_t)(b*L_+ls)*PROJ_DIM + DSSM + c] * cw[c*MK + k];
    }
    s = mupf*s + cb[c];
    out[idx] = siluf(s);
}

// ---------------- Mamba2 selective scan ----------------
#define SCT 32
__global__ __launch_bounds__(256) void scan_kernel(
    const float* __restrict__ conv, const float* __restrict__ proj,
    const float* __restrict__ A_log, const float* __restrict__ dt_bias,
    const float* __restrict__ Dp, float* __restrict__ y)
{
    const int b = blockIdx.x / MH, h = blockIdx.x % MH;
    const int tid = threadIdx.x;
    const int p = tid >> 2, sg = tid & 3, s0 = sg*16;
    const float Ah = -__expf(A_log[h]);
    const float Dh = Dp[h];
    const float dtb = dt_bias[h];
    float st[16];
    #pragma unroll
    for (int i = 0; i < 16; ++i) st[i] = 0.f;

    __shared__ float xs[SCT][64], Bsh[SCT][64], Csh[SCT][64], dts[SCT];

    for (int l0 = 0; l0 < L_; l0 += SCT) {
        __syncthreads();
        for (int i = tid; i < SCT*64; i += 256) {
            int t = i >> 6, c = i & 63;
            size_t base = (size_t)(b*L_ + l0 + t)*CONV_DIM;
            xs[t][c]  = conv[base + h*64 + c];
            Bsh[t][c] = conv[base + DSSM + c];
            Csh[t][c] = conv[base + DSSM + MS + c];
        }
        for (int i = tid; i < SCT; i += 256) {
            float r = proj[(size_t)(b*L_ + l0 + i)*PROJ_DIM + (PROJ_DIM-MH) + h] * 1.2f + dtb;
            dts[i] = (r > 20.f) ? r : log1pf(expf(r));   // softplus
        }
        __syncthreads();
        for (int t = 0; t < SCT; ++t) {
            float dt = dts[t];
            float dA = __expf(dt * Ah);
            float xv = xs[t][p];
            float coef = dt * xv;
            float acc = 0.f;
            #pragma unroll
            for (int ss = 0; ss < 16; ++ss) {
                st[ss] = st[ss]*dA + coef*Bsh[t][s0+ss];
                acc = fmaf(st[ss], Csh[t][s0+ss], acc);
            }
            acc += __shfl_xor_sync(0xffffffffu, acc, 1);
            acc += __shfl_xor_sync(0xffffffffu, acc, 2);
            if (sg == 0)
                y[(size_t)(b*L_ + l0 + t)*DSSM + h*64 + p] = acc + xv*Dh;
        }
    }
}

// ---------------- gating + RMS -> fp16 ----------------
__global__ __launch_bounds__(256) void gate_rms_kernel(
    const float* __restrict__ y, const float* __restrict__ proj,
    const float* __restrict__ w, __half* __restrict__ out)
{
    int m = blockIdx.x;
    const float* yr = y + (size_t)m*DSSM;
    const float* zr = proj + (size_t)m*PROJ_DIM;
    float v[8]; float ss = 0.f;
    #pragma unroll
    for (int k = 0; k < 8; ++k) {
        int c = threadIdx.x + k*256;
        float z = zr[c];
        float gv = yr[c] * siluf(z);
        v[k] = gv; ss += gv*gv;
    }
    ss = blockReduceSum256(ss);
    __shared__ float s_inv;
    if (threadIdx.x == 0) s_inv = rsqrtf(ss * (1.f/DSSM) + EPS_);
    __syncthreads();
    float inv = s_inv;
    __half* o = out + (size_t)m*DSSM;
    #pragma unroll
    for (int k = 0; k < 8; ++k) { int c = threadIdx.x + k*256; o[c] = __float2half_rn(v[k]*inv*w[c]); }
}

// ---------------- combine: h = as + residual ; hn16 = f16(rms(h)*w) ----------------
__global__ __launch_bounds__(256) void combine_kernel(
    const float* __restrict__ as_, const float* __restrict__ resid,
    const float* __restrict__ w, float* __restrict__ h, __half* __restrict__ hn)
{
    int m = blockIdx.x;
    const float* ar = as_  + (size_t)m*HID;
    const float* rr = resid + (size_t)m*HID;
    float v[8]; float ss = 0.f;
    #pragma unroll
    for (int k = 0; k < 8; ++k) {
        int c = threadIdx.x + k*256;
        float hv = ar[c] + rr[c];
        v[k] = hv; ss += hv*hv;
    }
    ss = blockReduceSum256(ss);
    __shared__ float s_inv;
    if (threadIdx.x == 0) s_inv = rsqrtf(ss * (1.f/HID) + EPS_);
    __syncthreads();
    float inv = s_inv;
    float* ho = h + (size_t)m*HID;
    __half* no = hn + (size_t)m*HID;
    #pragma unroll
    for (int k = 0; k < 8; ++k) {
        int c = threadIdx.x + k*256;
        ho[c] = v[k];
        no[c] = __float2half_rn(v[k]*inv*w[c]);
    }
}

// ---------------- SwiGLU activation -> fp16 ----------------
__global__ void act_kernel(const float* __restrict__ gu, __half* __restrict__ act) {
    int idx = blockIdx.x*256 + threadIdx.x;
    if (idx >= MROWS*INTER) return;
    int m = idx / INTER, i = idx % INTER;
    const float* row = gu + (size_t)m*(2*INTER);
    float gate = row[i] * GATE_MULT;
    float up   = row[INTER + i];
    act[idx] = __float2half_rn(siluf(gate) * up);
}

// ---------------- host launcher ----------------
extern "C" void kernel_launch(void* const* d_in, const int* in_sizes, int n_in,
                              void* d_out, int out_size)
{
    const float* hidden      = (const float*)d_in[0];
    const int*   positions   = (const int*)  d_in[1];
    const float* w_in_ln     = (const float*)d_in[2];
    const float* qkv_w       = (const float*)d_in[3];
    const float* o_w         = (const float*)d_in[4];
    const float* in_proj_w   = (const float*)d_in[5];
    const float* conv_w      = (const float*)d_in[6];
    const float* conv_b      = (const float*)d_in[7];
    const float* A_log       = (const float*)d_in[8];
    const float* dt_bias     = (const float*)d_in[9];
    const float* Dp          = (const float*)d_in[10];
    const float* ssm_norm_w  = (const float*)d_in[11];
    const float* out_proj_w  = (const float*)d_in[12];
    const float* w_pre_ff_ln = (const float*)d_in[13];
    const float* gate_up_w   = (const float*)d_in[14];
    const float* down_w      = (const float*)d_in[15];
    float* out = (float*)d_out;

    float *qkv, *proj, *conv, *y, *as_, *h, *gu;
    __half *hs16, *ctx16, *gt16, *hn16, *act16, *w16, *q16, *k16, *v16t;
    cudaGetSymbolAddress((void**)&qkv,  g_qkv);
    cudaGetSymbolAddress((void**)&proj, g_proj);
    cudaGetSymbolAddress((void**)&conv, g_conv);
    cudaGetSymbolAddress((void**)&y,    g_y);
    cudaGetSymbolAddress((void**)&as_,  g_as);
    cudaGetSymbolAddress((void**)&h,    g_h);
    cudaGetSymbolAddress((void**)&gu,   g_gu);
    cudaGetSymbolAddress((void**)&hs16, g_hs16);
    cudaGetSymbolAddress((void**)&ctx16,g_ctx16);
    cudaGetSymbolAddress((void**)&gt16, g_gt16);
    cudaGetSymbolAddress((void**)&hn16, g_hn16);
    cudaGetSymbolAddress((void**)&act16,g_act16);
    cudaGetSymbolAddress((void**)&w16,  g_w16);
    cudaGetSymbolAddress((void**)&q16,  g_q16);
    cudaGetSymbolAddress((void**)&k16,  g_k16);
    cudaGetSymbolAddress((void**)&v16t, g_v16t);

    cudaFuncSetAttribute(gemm_f16, cudaFuncAttributeMaxDynamicSharedMemorySize, GSMEM_BYTES);

    const int MT = MROWS/TBM;   // 16

    // 0. weight conversion fp32 -> fp16
    #define CVT(src, dstoff, n) \
        cvt_f16_kernel<<<((n)/4 + 255)/256, 256>>>(src, w16 + (size_t)(dstoff), (n)/4)
    CVT(qkv_w,      W16_QKV,     QKV_DIM*HID);
    CVT(in_proj_w,  W16_INPROJ,  PROJ_DIM*HID);
    CVT(o_w,        W16_O,       HID*HID);
    CVT(out_proj_w, W16_OUTPROJ, HID*DSSM);
    CVT(gate_up_w,  W16_GATEUP,  2*INTER*HID);
    CVT(down_w,     W16_DOWN,    HID*INTER);
    #undef CVT

    // 1. input RMS norm (fp16 out)
    rms_kernel<<<MROWS, 256>>>(hidden, w_in_ln, hs16);

    // 2. qkv = (hs*ATTN_IN) @ qkv_w^T ; proj = (hs*SSM_IN) @ in_proj_w^T
    gemm_f16<<<dim3(QKV_DIM/TBN, MT), 256, GSMEM_BYTES>>>(QKV_DIM, HID, ATTN_IN,
                                            hs16, w16 + W16_QKV, 0.f, nullptr, qkv);
    gemm_f16<<<dim3((PROJ_DIM+TBN-1)/TBN, MT), 256, GSMEM_BYTES>>>(PROJ_DIM, HID, SSM_IN,
                                            hs16, w16 + W16_INPROJ, 0.f, nullptr, proj);

    // 3. RoPE -> fp16 q/k ; V transpose -> fp16
    rope_kernel<<<(MROWS*(NH+NKV)*32 + 255)/256, 256>>>(qkv, positions, q16, k16);
    vtrans_kernel<<<dim3(L_/64, NKV, B_), 256>>>(qkv, v16t);

    // 4. tensor-core flash attention (fp16 ctx out)
    attn_kernel<<<dim3(L_/64, NH, B_), 128>>>(q16, k16, v16t, ctx16);

    // 5. as = ATTN_OUT * ctx @ o_w^T
    gemm_f16<<<dim3(HID/TBN, MT), 256, GSMEM_BYTES>>>(HID, HID, ATTN_OUT,
                                            ctx16, w16 + W16_O, 0.f, nullptr, as_);

    // 6. mamba
    conv_kernel<<<(MROWS*CONV_DIM + 255)/256, 256>>>(proj, conv_w, conv_b, conv);
    scan_kernel<<<B_*MH, 256>>>(conv, proj, A_log, dt_bias, Dp, y);
    gate_rms_kernel<<<MROWS, 256>>>(y, proj, ssm_norm_w, gt16);
    gemm_f16<<<dim3(HID/TBN, MT), 256, GSMEM_BYTES>>>(HID, DSSM, SSM_OUT,
                                            gt16, w16 + W16_OUTPROJ, 1.f, as_, as_);

    // 7. combine + pre-FF RMS (fp16 hn out)
    combine_kernel<<<MROWS, 256>>>(as_, hidden, w_pre_ff_ln, h, hn16);

    // 8. MLP
    gemm_f16<<<dim3(2*INTER/TBN, MT), 256, GSMEM_BYTES>>>(2*INTER, HID, 1.f,
                                            hn16, w16 + W16_GATEUP, 0.f, nullptr, gu);
    act_kernel<<<(MROWS*INTER + 255)/256, 256>>>(gu, act16);
    gemm_f16<<<dim3(HID/TBN, MT), 256, GSMEM_BYTES>>>(HID, INTER, DOWN_MULT,
                                            act16, w16 + W16_DOWN, 1.f, h, out);
    (void)in_sizes; (void)n_in; (void)out_size;
}